// round 13
// baseline (speedup 1.0000x reference)
#include <cuda_runtime.h>
#include <cuda_bf16.h>
#include <cuda_fp16.h>
#include <cuda_fp8.h>
#include <math.h>

// Problem constants (fixed by the reference)
#define N_NODES 50000
#define E_MAX   800000
#define IN_C    128
#define HID     64
#define HEADS   4
#define F1      (HEADS*HID)   // 256
#define OUT_C   64
#define NUM_CLASSES 40

#define SCAN_BLOCK 1024
#define SCAN_NBLK  ((N_NODES + SCAN_BLOCK - 1) / SCAN_BLOCK)   // 49

// ----------------------------------------------------------------------------
// Scratch (device globals: allocation-free per harness rules)
// ----------------------------------------------------------------------------
__device__ unsigned char g_h1q[(size_t)N_NODES * F1];  // layer-1 features, fp8 e4m3
__device__ __half g_x2h[(size_t)N_NODES * F1];         // layer-1 GAT output, fp16
__device__ __half g_h2h[(size_t)N_NODES * OUT_C];      // layer-2 features, fp16
__device__ __half g_w1hT[(size_t)F1 * IN_C];           // W1^T hi  [n][k]
__device__ __half g_w1lT[(size_t)F1 * IN_C];           // W1^T lo
__device__ __half g_w2hT[(size_t)OUT_C * F1];          // W2^T hi
__device__ __half g_w2lT[(size_t)OUT_C * F1];          // W2^T lo
__device__ float  g_as1[N_NODES * HEADS];
__device__ float  g_ad1[N_NODES * HEADS];
__device__ float  g_as2[N_NODES];
__device__ float  g_ad2[N_NODES];
__device__ int    g_counts[N_NODES + 1];
__device__ int    g_rowptr[N_NODES + 1];
__device__ int    g_cursor[N_NODES];
__device__ int    g_src32[E_MAX];
__device__ int    g_dst32[E_MAX];
__device__ int    g_csr_src[E_MAX];
__device__ unsigned long long g_scan_pkt[SCAN_NBLK];   // lookback: (status<<32)|value
__device__ float  g_pooled[OUT_C];
__device__ int    g_done;
__device__ int    g_is64;

__device__ __forceinline__ float lrelu(float v) { return v > 0.f ? v : 0.2f * v; }

__device__ __forceinline__ void split_h(float v, __half& hi, __half& lo) {
    hi = __float2half(v);
    lo = __float2half(v - __half2float(hi));
}

__device__ __forceinline__ float2 fp8x2_to_float2(unsigned short v) {
    __half2_raw hr = __nv_cvt_fp8x2_to_halfraw2((__nv_fp8x2_storage_t)v, __NV_E4M3);
    return __half22float2(*reinterpret_cast<__half2*>(&hr));
}

// m16n8k16 fp16 MMA, fp32 accumulate
__device__ __forceinline__ void mma_f16(float* c, const unsigned* a, const unsigned* b) {
    asm volatile(
        "mma.sync.aligned.m16n8k16.row.col.f32.f16.f16.f32 "
        "{%0,%1,%2,%3}, {%4,%5,%6,%7}, {%8,%9}, {%0,%1,%2,%3};\n"
        : "+f"(c[0]), "+f"(c[1]), "+f"(c[2]), "+f"(c[3])
        : "r"(a[0]), "r"(a[1]), "r"(a[2]), "r"(a[3]), "r"(b[0]), "r"(b[1]));
}

// ----------------------------------------------------------------------------
// W pre-split + transpose: W1[k][n] -> w1{h,l}T[n][k]; W2 likewise. Tiny.
// ----------------------------------------------------------------------------
__global__ void wsplit_kernel(const float* __restrict__ W1,
                              const float* __restrict__ W2) {
    int i = blockIdx.x * blockDim.x + threadIdx.x;
    if (i < IN_C * F1) {
        int k = i / F1, n = i % F1;
        __half h, l; split_h(W1[i], h, l);
        g_w1hT[(size_t)n * IN_C + k] = h;
        g_w1lT[(size_t)n * IN_C + k] = l;
    }
    if (i < F1 * OUT_C) {
        int k = i / OUT_C, n = i % OUT_C;
        __half h, l; split_h(W2[i], h, l);
        g_w2hT[(size_t)n * F1 + k] = h;
        g_w2lT[(size_t)n * F1 + k] = l;
    }
}

// ----------------------------------------------------------------------------
// 0+1) init (zero counts + pooled + scan state + done flag) and dtype detect
// ----------------------------------------------------------------------------
__global__ void init_detect_kernel(const int* __restrict__ ei) {
    int i = blockIdx.x * blockDim.x + threadIdx.x;
    if (i < N_NODES + 1) g_counts[i] = 0;
    if (i < OUT_C)       g_pooled[i] = 0.f;
    if (i < SCAN_NBLK)   g_scan_pkt[i] = 0ULL;
    if (i == 0)          g_done = 0;
    if (blockIdx.x == 0) {
        __shared__ int any;
        if (threadIdx.x == 0) any = 0;
        __syncthreads();
        for (int j = threadIdx.x; j < 4096; j += blockDim.x) {
            if (ei[2 * j + 1] != 0) any = 1;
        }
        __syncthreads();
        if (threadIdx.x == 0) g_is64 = (any == 0) ? 1 : 0;
    }
}

// ----------------------------------------------------------------------------
// 2) convert to int32 + count in-degrees
// ----------------------------------------------------------------------------
__global__ void convert_count_kernel(const void* __restrict__ ei, int E) {
    int e = blockIdx.x * blockDim.x + threadIdx.x;
    if (e >= E) return;
    int s, d;
    if (g_is64) {
        const long long* p = (const long long*)ei;
        s = (int)p[e]; d = (int)p[E + e];
    } else {
        const int* p = (const int*)ei;
        s = p[e]; d = p[E + e];
    }
    g_src32[e] = s;
    g_dst32[e] = d;
    atomicAdd(&g_counts[d], 1);
}

// ----------------------------------------------------------------------------
// 3) single-pass decoupled-lookback exclusive scan -> g_rowptr / g_cursor
//    49 blocks, all concurrently resident (148 SMs) -> no deadlock.
// ----------------------------------------------------------------------------
__global__ void __launch_bounds__(SCAN_BLOCK) scan_lookback_kernel() {
    int b = blockIdx.x, t = threadIdx.x;
    int i = b * SCAN_BLOCK + t;
    int v = (i < N_NODES) ? g_counts[i] : 0;
    int lane = t & 31, w = t >> 5;
    int inc = v;
#pragma unroll
    for (int o = 1; o < 32; o <<= 1) {
        int u = __shfl_up_sync(~0u, inc, o);
        if (lane >= o) inc += u;
    }
    __shared__ int wsum[32];
    if (lane == 31) wsum[w] = inc;
    __syncthreads();
    if (w == 0) {
        int s = wsum[lane];
#pragma unroll
        for (int o = 1; o < 32; o <<= 1) {
            int u = __shfl_up_sync(~0u, s, o);
            if (lane >= o) s += u;
        }
        wsum[lane] = s;
    }
    __syncthreads();
    const int block_total = wsum[31];

    __shared__ int sbase;
    if (t == 0) {
        if (b == 0) {
            atomicExch(&g_scan_pkt[0],
                       (2ULL << 32) | (unsigned long long)(unsigned)block_total);
            sbase = 0;
        } else {
            atomicExch(&g_scan_pkt[b],
                       (1ULL << 32) | (unsigned long long)(unsigned)block_total);
            int excl = 0;
            int j = b - 1;
            while (true) {
                unsigned long long p = atomicAdd(&g_scan_pkt[j], 0ULL);
                unsigned st = (unsigned)(p >> 32);
                if (st == 0u) continue;          // predecessor not published yet
                excl += (int)(unsigned)p;
                if (st == 2u) break;             // inclusive prefix found
                j--;
            }
            atomicExch(&g_scan_pkt[b],
                       (2ULL << 32) | (unsigned long long)(unsigned)(excl + block_total));
            sbase = excl;
        }
    }
    __syncthreads();
    int base = sbase;
    int exc = base + inc - v + (w > 0 ? wsum[w - 1] : 0);
    if (i < N_NODES) {
        g_rowptr[i] = exc;
        g_cursor[i] = exc;
    }
    if (b == SCAN_NBLK - 1 && t == SCAN_BLOCK - 1)
        g_rowptr[N_NODES] = base + block_total;
}

// ----------------------------------------------------------------------------
// 4) fill CSR (src indices grouped by dst)
// ----------------------------------------------------------------------------
__global__ void fill_kernel(int E) {
    int e = blockIdx.x * blockDim.x + threadIdx.x;
    if (e >= E) return;
    int pos = atomicAdd(&g_cursor[g_dst32[e]], 1);
    g_csr_src[pos] = g_src32[e];
}

// ----------------------------------------------------------------------------
// GEMM1 fused (3xFP16 HMMA): h1 = x @ W1  (50000x128 @ 128x256)  (PROVEN r10)
// ----------------------------------------------------------------------------
__global__ void __launch_bounds__(256) gemm1_fused(const float* __restrict__ A,
                                                   const float* __restrict__ att_s,
                                                   const float* __restrict__ att_d) {
    constexpr int M = N_NODES, K = IN_C;
    constexpr int BM = 128, BN = 128, BK = 32;
    constexpr int SKA = BK + 8;
    __shared__ __half Ah[BM][SKA], Al[BM][SKA];
    __shared__ __half BhT[BN][SKA], BlT[BN][SKA];
    __shared__ float satt_s[BN], satt_d[BN];

    const int tid = threadIdx.x;
    const int lane = tid & 31, warp = tid >> 5;
    const int g = lane >> 2, t = lane & 3;
    const int warp_m = warp & 3;
    const int warp_n = warp >> 2;
    const int block_row = blockIdx.y * BM;
    const int block_col = blockIdx.x * BN;

    if (tid < BN) {
        satt_s[tid] = att_s[block_col + tid];
        satt_d[tid] = att_d[block_col + tid];
    }

    float acc[2][8][4];
#pragma unroll
    for (int mt = 0; mt < 2; mt++)
#pragma unroll
        for (int nt = 0; nt < 8; nt++)
#pragma unroll
            for (int q = 0; q < 4; q++) acc[mt][nt][q] = 0.f;

    for (int k0 = 0; k0 < K; k0 += BK) {
#pragma unroll
        for (int it = 0; it < 4; it++) {
            int idx = tid + it * 256;
            int r  = idx >> 3;
            int c4 = idx & 7;
            int gr = block_row + r;
            float4 v = make_float4(0.f, 0.f, 0.f, 0.f);
            if (gr < M) v = *(const float4*)(A + (size_t)gr * K + k0 + c4 * 4);
            __half h0, l0, h1, l1, h2, l2, h3, l3;
            split_h(v.x, h0, l0); split_h(v.y, h1, l1);
            split_h(v.z, h2, l2); split_h(v.w, h3, l3);
            int c = c4 * 4;
            Ah[r][c + 0] = h0; Ah[r][c + 1] = h1; Ah[r][c + 2] = h2; Ah[r][c + 3] = h3;
            Al[r][c + 0] = l0; Al[r][c + 1] = l1; Al[r][c + 2] = l2; Al[r][c + 3] = l3;
        }
#pragma unroll
        for (int it = 0; it < 2; it++) {
            int idx = tid + it * 256;
            int n = idx >> 2, c8 = idx & 3;
            *(uint4*)&BhT[n][c8 * 8] =
                *(const uint4*)&g_w1hT[(size_t)(block_col + n) * K + k0 + c8 * 8];
        }
#pragma unroll
        for (int it = 0; it < 2; it++) {
            int idx = tid + it * 256;
            int n = idx >> 2, c8 = idx & 3;
            *(uint4*)&BlT[n][c8 * 8] =
                *(const uint4*)&g_w1lT[(size_t)(block_col + n) * K + k0 + c8 * 8];
        }
        __syncthreads();
#pragma unroll
        for (int ks = 0; ks < 2; ks++) {
            const int kk = ks * 16;
            unsigned ah[2][4], al[2][4];
#pragma unroll
            for (int mt = 0; mt < 2; mt++) {
                int r0 = warp_m * 32 + mt * 16 + g;
                ah[mt][0] = *(const unsigned*)&Ah[r0][kk + 2 * t];
                ah[mt][1] = *(const unsigned*)&Ah[r0 + 8][kk + 2 * t];
                ah[mt][2] = *(const unsigned*)&Ah[r0][kk + 2 * t + 8];
                ah[mt][3] = *(const unsigned*)&Ah[r0 + 8][kk + 2 * t + 8];
                al[mt][0] = *(const unsigned*)&Al[r0][kk + 2 * t];
                al[mt][1] = *(const unsigned*)&Al[r0 + 8][kk + 2 * t];
                al[mt][2] = *(const unsigned*)&Al[r0][kk + 2 * t + 8];
                al[mt][3] = *(const unsigned*)&Al[r0 + 8][kk + 2 * t + 8];
            }
#pragma unroll
            for (int nt = 0; nt < 8; nt++) {
                int n0 = warp_n * 64 + nt * 8 + g;
                unsigned bh[2], bl[2];
                bh[0] = *(const unsigned*)&BhT[n0][kk + 2 * t];
                bh[1] = *(const unsigned*)&BhT[n0][kk + 2 * t + 8];
                bl[0] = *(const unsigned*)&BlT[n0][kk + 2 * t];
                bl[1] = *(const unsigned*)&BlT[n0][kk + 2 * t + 8];
#pragma unroll
                for (int mt = 0; mt < 2; mt++) {
                    mma_f16(acc[mt][nt], ah[mt], bl);
                    mma_f16(acc[mt][nt], al[mt], bh);
                    mma_f16(acc[mt][nt], ah[mt], bh);
                }
            }
        }
        __syncthreads();
    }

    const int head = blockIdx.x * 2 + warp_n;
#pragma unroll
    for (int mt = 0; mt < 2; mt++) {
#pragma unroll
        for (int rr = 0; rr < 2; rr++) {
            int grow = block_row + warp_m * 32 + mt * 16 + g + rr * 8;
            bool valid = grow < M;
            float as_p = 0.f, ad_p = 0.f;
#pragma unroll
            for (int nt = 0; nt < 8; nt++) {
                float v0 = acc[mt][nt][rr * 2 + 0];
                float v1 = acc[mt][nt][rr * 2 + 1];
                int col = warp_n * 64 + nt * 8 + 2 * t;
                as_p += v0 * satt_s[col] + v1 * satt_s[col + 1];
                ad_p += v0 * satt_d[col] + v1 * satt_d[col + 1];
                if (valid) {
                    __nv_fp8x2_storage_t p = __nv_cvt_float2_to_fp8x2(
                        make_float2(v0, v1), __NV_SATFINITE, __NV_E4M3);
                    *(unsigned short*)&g_h1q[(size_t)grow * F1 + block_col + col] =
                        (unsigned short)p;
                }
            }
            as_p += __shfl_xor_sync(0xffffffffu, as_p, 1);
            as_p += __shfl_xor_sync(0xffffffffu, as_p, 2);
            ad_p += __shfl_xor_sync(0xffffffffu, ad_p, 1);
            ad_p += __shfl_xor_sync(0xffffffffu, ad_p, 2);
            if (t == 0 && valid) {
                g_as1[grow * HEADS + head] = as_p;
                g_ad1[grow * HEADS + head] = ad_p;
            }
        }
    }
}

// ----------------------------------------------------------------------------
// GEMM2 fused (2xFP16 HMMA, exact fp16 A): h2 = x2h @ W2  (PROVEN r10)
// ----------------------------------------------------------------------------
__global__ void __launch_bounds__(128) gemm2_fused(const float* __restrict__ att_s,
                                                   const float* __restrict__ att_d) {
    constexpr int M = N_NODES, K = F1;
    constexpr int BM = 128, BN = 64, BK = 32;
    constexpr int SKA = BK + 8;
    const __half* A = g_x2h;
    __shared__ __half Ah[BM][SKA];
    __shared__ __half BhT[BN][SKA], BlT[BN][SKA];
    __shared__ float satt_s[BN], satt_d[BN];

    const int tid = threadIdx.x;
    const int lane = tid & 31, warp = tid >> 5;
    const int g = lane >> 2, t = lane & 3;
    const int block_row = blockIdx.y * BM;

    if (tid < BN) {
        satt_s[tid] = att_s[tid];
        satt_d[tid] = att_d[tid];
    }

    float acc[2][8][4];
#pragma unroll
    for (int mt = 0; mt < 2; mt++)
#pragma unroll
        for (int nt = 0; nt < 8; nt++)
#pragma unroll
            for (int q = 0; q < 4; q++) acc[mt][nt][q] = 0.f;

    for (int k0 = 0; k0 < K; k0 += BK) {
#pragma unroll
        for (int it = 0; it < 4; it++) {
            int idx = tid + it * 128;
            int r  = idx >> 2;
            int c8 = idx & 3;
            int gr = block_row + r;
            uint4 v = make_uint4(0u, 0u, 0u, 0u);
            if (gr < M) v = *(const uint4*)(A + (size_t)gr * K + k0 + c8 * 8);
            *(uint4*)&Ah[r][c8 * 8] = v;
        }
#pragma unroll
        for (int it = 0; it < 2; it++) {
            int idx = tid + it * 128;
            int n = idx >> 2, c8 = idx & 3;
            *(uint4*)&BhT[n][c8 * 8] =
                *(const uint4*)&g_w2hT[(size_t)n * K + k0 + c8 * 8];
        }
#pragma unroll
        for (int it = 0; it < 2; it++) {
            int idx = tid + it * 128;
            int n = idx >> 2, c8 = idx & 3;
            *(uint4*)&BlT[n][c8 * 8] =
                *(const uint4*)&g_w2lT[(size_t)n * K + k0 + c8 * 8];
        }
        __syncthreads();
#pragma unroll
        for (int ks = 0; ks < 2; ks++) {
            const int kk = ks * 16;
            unsigned ah[2][4];
#pragma unroll
            for (int mt = 0; mt < 2; mt++) {
                int r0 = warp * 32 + mt * 16 + g;
                ah[mt][0] = *(const unsigned*)&Ah[r0][kk + 2 * t];
                ah[mt][1] = *(const unsigned*)&Ah[r0 + 8][kk + 2 * t];
                ah[mt][2] = *(const unsigned*)&Ah[r0][kk + 2 * t + 8];
                ah[mt][3] = *(const unsigned*)&Ah[r0 + 8][kk + 2 * t + 8];
            }
#pragma unroll
            for (int nt = 0; nt < 8; nt++) {
                int n0 = nt * 8 + g;
                unsigned bh[2], bl[2];
                bh[0] = *(const unsigned*)&BhT[n0][kk + 2 * t];
                bh[1] = *(const unsigned*)&BhT[n0][kk + 2 * t + 8];
                bl[0] = *(const unsigned*)&BlT[n0][kk + 2 * t];
                bl[1] = *(const unsigned*)&BlT[n0][kk + 2 * t + 8];
#pragma unroll
                for (int mt = 0; mt < 2; mt++) {
                    mma_f16(acc[mt][nt], ah[mt], bl);
                    mma_f16(acc[mt][nt], ah[mt], bh);
                }
            }
        }
        __syncthreads();
    }

#pragma unroll
    for (int mt = 0; mt < 2; mt++) {
#pragma unroll
        for (int rr = 0; rr < 2; rr++) {
            int grow = block_row + warp * 32 + mt * 16 + g + rr * 8;
            bool valid = grow < M;
            float as_p = 0.f, ad_p = 0.f;
#pragma unroll
            for (int nt = 0; nt < 8; nt++) {
                float v0 = acc[mt][nt][rr * 2 + 0];
                float v1 = acc[mt][nt][rr * 2 + 1];
                int col = nt * 8 + 2 * t;
                as_p += v0 * satt_s[col] + v1 * satt_s[col + 1];
                ad_p += v0 * satt_d[col] + v1 * satt_d[col + 1];
                if (valid) {
                    __half2 hv = __floats2half2_rn(v0, v1);
                    *(__half2*)&g_h2h[(size_t)grow * OUT_C + col] = hv;
                }
            }
            as_p += __shfl_xor_sync(0xffffffffu, as_p, 1);
            as_p += __shfl_xor_sync(0xffffffffu, as_p, 2);
            ad_p += __shfl_xor_sync(0xffffffffu, ad_p, 1);
            ad_p += __shfl_xor_sync(0xffffffffu, ad_p, 2);
            if (t == 0 && valid) {
                g_as2[grow] = as_p;
                g_ad2[grow] = ad_p;
            }
        }
    }
}

// ----------------------------------------------------------------------------
// Layer-1 aggregation (PROVEN r10 loop): warp per dst node, single-pass
// softmax, FP8 gathers, fp32 accumulation, fp16 x2 output.
// ----------------------------------------------------------------------------
__global__ void agg1_kernel(const float* __restrict__ b1) {
    int t = threadIdx.x;
    int warp = (blockIdx.x * blockDim.x + t) >> 5;
    if (warp >= N_NODES) return;
    int lane = t & 31;
    int d = warp;
    int head = lane >> 3;

    float ad = g_ad1[d * HEADS + head];
    int beg = g_rowptr[d], end = g_rowptr[d + 1];

    float denom = 1e-16f;
    float acc[8] = {0.f, 0.f, 0.f, 0.f, 0.f, 0.f, 0.f, 0.f};
    for (int i = beg; i < end; i++) {
        int s = g_csr_src[i];
        float w = __expf(lrelu(g_as1[s * HEADS + head] + ad));
        denom += w;
        uint2 u = *(const uint2*)&g_h1q[(size_t)s * F1 + lane * 8];
        float2 f0 = fp8x2_to_float2((unsigned short)(u.x & 0xffffu));
        float2 f1 = fp8x2_to_float2((unsigned short)(u.x >> 16));
        float2 f2 = fp8x2_to_float2((unsigned short)(u.y & 0xffffu));
        float2 f3 = fp8x2_to_float2((unsigned short)(u.y >> 16));
        acc[0] += w * f0.x; acc[1] += w * f0.y;
        acc[2] += w * f1.x; acc[3] += w * f1.y;
        acc[4] += w * f2.x; acc[5] += w * f2.y;
        acc[6] += w * f3.x; acc[7] += w * f3.y;
    }
    {   // self loop
        float w = __expf(lrelu(g_as1[d * HEADS + head] + ad));
        denom += w;
        uint2 u = *(const uint2*)&g_h1q[(size_t)d * F1 + lane * 8];
        float2 f0 = fp8x2_to_float2((unsigned short)(u.x & 0xffffu));
        float2 f1 = fp8x2_to_float2((unsigned short)(u.x >> 16));
        float2 f2 = fp8x2_to_float2((unsigned short)(u.y & 0xffffu));
        float2 f3 = fp8x2_to_float2((unsigned short)(u.y >> 16));
        acc[0] += w * f0.x; acc[1] += w * f0.y;
        acc[2] += w * f1.x; acc[3] += w * f1.y;
        acc[4] += w * f2.x; acc[5] += w * f2.y;
        acc[6] += w * f3.x; acc[7] += w * f3.y;
    }
    float inv = 1.f / denom;
    int cb = lane * 8;
    __half hbuf[8];
#pragma unroll
    for (int j = 0; j < 8; j++)
        hbuf[j] = __float2half(fmaxf(acc[j] * inv + b1[cb + j], 0.f));
    *(uint4*)&g_x2h[(size_t)d * F1 + cb] = *(uint4*)hbuf;
}

// ----------------------------------------------------------------------------
// Layer-2 aggregation (PROVEN r10 loop) + pool + FUSED final epilogue
// (fence + atomic counter; last block computes FC + log_softmax).
// ----------------------------------------------------------------------------
__global__ void agg2_pool_final_kernel(const float* __restrict__ b2,
                                       const float* __restrict__ fc_w,
                                       const float* __restrict__ fc_b,
                                       float* __restrict__ out) {
    __shared__ float sp[OUT_C];
    int t = threadIdx.x;
    if (t < OUT_C) sp[t] = 0.f;
    __syncthreads();

    int warp = (blockIdx.x * blockDim.x + t) >> 5;
    int lane = t & 31;
    if (warp < N_NODES) {
        int d = warp;
        float ad = g_ad2[d];
        int beg = g_rowptr[d], end = g_rowptr[d + 1];

        float denom = 1e-16f;
        float a0 = 0.f, a1 = 0.f;
        for (int i = beg; i < end; i++) {
            int s = g_csr_src[i];
            float w = __expf(lrelu(g_as2[s] + ad));
            denom += w;
            a0 += w * __half2float(g_h2h[(size_t)s * OUT_C + lane]);
            a1 += w * __half2float(g_h2h[(size_t)s * OUT_C + 32 + lane]);
        }
        {
            float w = __expf(lrelu(g_as2[d] + ad));
            denom += w;
            a0 += w * __half2float(g_h2h[(size_t)d * OUT_C + lane]);
            a1 += w * __half2float(g_h2h[(size_t)d * OUT_C + 32 + lane]);
        }
        float inv = 1.f / denom;
        float v0 = fmaxf(a0 * inv + b2[lane], 0.f);
        float v1 = fmaxf(a1 * inv + b2[32 + lane], 0.f);
        atomicAdd(&sp[lane], v0);
        atomicAdd(&sp[32 + lane], v1);
    }
    __syncthreads();
    if (t < OUT_C) atomicAdd(&g_pooled[t], sp[t]);

    // ---- last-block final epilogue ----
    __shared__ bool is_last;
    if (t == 0) {
        __threadfence();
        int v = atomicAdd(&g_done, 1);
        is_last = (v == (int)gridDim.x - 1);
    }
    __syncthreads();
    if (is_last) {
        __shared__ float p[OUT_C];
        __shared__ float lg[NUM_CLASSES];
        __shared__ float lse_sh;
        if (t < OUT_C) p[t] = atomicAdd(&g_pooled[t], 0.f) * (1.0f / (float)N_NODES);
        __syncthreads();
        if (t < NUM_CLASSES) {
            float s = fc_b[t];
#pragma unroll
            for (int c = 0; c < OUT_C; c++) s += p[c] * fc_w[c * NUM_CLASSES + t];
            lg[t] = s;
        }
        __syncthreads();
        if (t == 0) {
            float mx = lg[0];
            for (int j = 1; j < NUM_CLASSES; j++) mx = fmaxf(mx, lg[j]);
            float se = 0.f;
            for (int j = 0; j < NUM_CLASSES; j++) se += expf(lg[j] - mx);
            lse_sh = mx + logf(se);
        }
        __syncthreads();
        if (t < NUM_CLASSES) out[t] = lg[t] - lse_sh;
    }
}

// ----------------------------------------------------------------------------
// launch: CSR build (side stream) overlaps wsplit+gemm1 (main stream).
// ----------------------------------------------------------------------------
extern "C" void kernel_launch(void* const* d_in, const int* in_sizes, int n_in,
                              void* d_out, int out_size) {
    const float* x      = (const float*)d_in[0];
    const void*  ei     = d_in[1];
    const float* W1     = (const float*)d_in[2];
    const float* att_s1 = (const float*)d_in[3];
    const float* att_d1 = (const float*)d_in[4];
    const float* b1     = (const float*)d_in[5];
    const float* W2     = (const float*)d_in[6];
    const float* att_s2 = (const float*)d_in[7];
    const float* att_d2 = (const float*)d_in[8];
    const float* b2     = (const float*)d_in[9];
    const float* fc_w   = (const float*)d_in[10];
    const float* fc_b   = (const float*)d_in[11];
    float* out = (float*)d_out;

    int E = in_sizes[1] / 2;
    if (E > E_MAX) E = E_MAX;

    const int WARPS_PER_BLOCK = 8;
    const int nodeBlocks = (N_NODES + WARPS_PER_BLOCK - 1) / WARPS_PER_BLOCK;
    const int mBlocks = (N_NODES + 127) / 128;

    static cudaStream_t s_side = nullptr;
    static cudaEvent_t  ev_fork = nullptr, ev_join = nullptr;
    if (s_side == nullptr) {
        cudaStreamCreateWithFlags(&s_side, cudaStreamNonBlocking);
        cudaEventCreateWithFlags(&ev_fork, cudaEventDisableTiming);
        cudaEventCreateWithFlags(&ev_join, cudaEventDisableTiming);
    }

    // Fork: CSR-build chain on side stream
    cudaEventRecord(ev_fork, 0);
    cudaStreamWaitEvent(s_side, ev_fork, 0);

    init_detect_kernel<<<(N_NODES + 256) / 256, 256, 0, s_side>>>((const int*)ei);
    convert_count_kernel<<<(E + 255) / 256, 256, 0, s_side>>>(ei, E);
    scan_lookback_kernel<<<SCAN_NBLK, SCAN_BLOCK, 0, s_side>>>();
    fill_kernel<<<(E + 255) / 256, 256, 0, s_side>>>(E);
    cudaEventRecord(ev_join, s_side);

    // Concurrent on main stream: weight split + layer-1 GEMM
    wsplit_kernel<<<(IN_C * F1 + 255) / 256, 256>>>(W1, W2);
    gemm1_fused<<<dim3(F1 / 128, mBlocks), 256>>>(x, att_s1, att_d1);

    // Join: agg1 needs both CSR and gemm1
    cudaStreamWaitEvent(0, ev_join, 0);

    agg1_kernel<<<nodeBlocks, 256>>>(b1);
    gemm2_fused<<<dim3(1, mBlocks), 128>>>(att_s2, att_d2);
    agg2_pool_final_kernel<<<nodeBlocks, 256>>>(b2, fc_w, fc_b, out);
}

// round 14
// speedup vs baseline: 1.0270x; 1.0270x over previous
#include <cuda_runtime.h>
#include <cuda_bf16.h>
#include <cuda_fp16.h>
#include <cuda_fp8.h>
#include <math.h>

// Problem constants (fixed by the reference)
#define N_NODES 50000
#define E_MAX   800000
#define IN_C    128
#define HID     64
#define HEADS   4
#define F1      (HEADS*HID)   // 256
#define OUT_C   64
#define NUM_CLASSES 40

#define SCAN_BLOCK 1024
#define SCAN_NBLK  ((N_NODES + SCAN_BLOCK - 1) / SCAN_BLOCK)   // 49

// ----------------------------------------------------------------------------
// Scratch (device globals: allocation-free per harness rules)
// ----------------------------------------------------------------------------
__device__ unsigned char g_h1q[(size_t)N_NODES * F1];  // layer-1 features, fp8 e4m3
__device__ __half g_x2h[(size_t)N_NODES * F1];         // layer-1 GAT output, fp16
__device__ __half g_h2h[(size_t)N_NODES * OUT_C];      // layer-2 features, fp16
__device__ __half g_w1hT[(size_t)F1 * IN_C];           // W1^T hi  [n][k]
__device__ __half g_w1lT[(size_t)F1 * IN_C];           // W1^T lo
__device__ __half g_w2hT[(size_t)OUT_C * F1];          // W2^T hi
__device__ __half g_w2lT[(size_t)OUT_C * F1];          // W2^T lo
__device__ float  g_as1[N_NODES * HEADS];
__device__ float  g_ad1[N_NODES * HEADS];
__device__ float  g_as2[N_NODES];
__device__ float  g_ad2[N_NODES];
__device__ int    g_counts[N_NODES + 1];
__device__ int    g_rowptr[N_NODES + 1];
__device__ int    g_cursor[N_NODES];
__device__ int    g_csr_src[E_MAX];
__device__ int    g_blksum[SCAN_NBLK];
__device__ int    g_blkoff[SCAN_NBLK];
__device__ float  g_pooled[OUT_C];
__device__ int    g_is64;

__device__ __forceinline__ float lrelu(float v) { return v > 0.f ? v : 0.2f * v; }

__device__ __forceinline__ void split_h(float v, __half& hi, __half& lo) {
    hi = __float2half(v);
    lo = __float2half(v - __half2float(hi));
}

__device__ __forceinline__ float2 fp8x2_to_float2(unsigned short v) {
    __half2_raw hr = __nv_cvt_fp8x2_to_halfraw2((__nv_fp8x2_storage_t)v, __NV_E4M3);
    return __half22float2(*reinterpret_cast<__half2*>(&hr));
}

// m16n8k16 fp16 MMA, fp32 accumulate
__device__ __forceinline__ void mma_f16(float* c, const unsigned* a, const unsigned* b) {
    asm volatile(
        "mma.sync.aligned.m16n8k16.row.col.f32.f16.f16.f32 "
        "{%0,%1,%2,%3}, {%4,%5,%6,%7}, {%8,%9}, {%0,%1,%2,%3};\n"
        : "+f"(c[0]), "+f"(c[1]), "+f"(c[2]), "+f"(c[3])
        : "r"(a[0]), "r"(a[1]), "r"(a[2]), "r"(a[3]), "r"(b[0]), "r"(b[1]));
}

// ----------------------------------------------------------------------------
// W pre-split + transpose: W1[k][n] -> w1{h,l}T[n][k]; W2 likewise. Tiny.
// ----------------------------------------------------------------------------
__global__ void wsplit_kernel(const float* __restrict__ W1,
                              const float* __restrict__ W2) {
    int i = blockIdx.x * blockDim.x + threadIdx.x;
    if (i < IN_C * F1) {
        int k = i / F1, n = i % F1;
        __half h, l; split_h(W1[i], h, l);
        g_w1hT[(size_t)n * IN_C + k] = h;
        g_w1lT[(size_t)n * IN_C + k] = l;
    }
    if (i < F1 * OUT_C) {
        int k = i / OUT_C, n = i % OUT_C;
        __half h, l; split_h(W2[i], h, l);
        g_w2hT[(size_t)n * F1 + k] = h;
        g_w2lT[(size_t)n * F1 + k] = l;
    }
}

// ----------------------------------------------------------------------------
// 0+1) init (zero counts + pooled) and int64/int32 detection, one launch
// ----------------------------------------------------------------------------
__global__ void init_detect_kernel(const int* __restrict__ ei) {
    int i = blockIdx.x * blockDim.x + threadIdx.x;
    if (i < N_NODES + 1) g_counts[i] = 0;
    if (i < OUT_C)       g_pooled[i] = 0.f;
    if (blockIdx.x == 0) {
        __shared__ int any;
        if (threadIdx.x == 0) any = 0;
        __syncthreads();
        for (int j = threadIdx.x; j < 4096; j += blockDim.x) {
            if (ei[2 * j + 1] != 0) any = 1;
        }
        __syncthreads();
        if (threadIdx.x == 0) g_is64 = (any == 0) ? 1 : 0;
    }
}

// ----------------------------------------------------------------------------
// 2) count in-degrees (reads edge_index directly; no staging arrays)
// ----------------------------------------------------------------------------
__global__ void count_kernel(const void* __restrict__ ei, int E) {
    int e = blockIdx.x * blockDim.x + threadIdx.x;
    if (e >= E) return;
    int d;
    if (g_is64) d = (int)((const long long*)ei)[E + e];
    else        d = ((const int*)ei)[E + e];
    atomicAdd(&g_counts[d], 1);
}

// ----------------------------------------------------------------------------
// 3) parallel exclusive scan of g_counts -> g_rowptr / g_cursor  (PROVEN r4)
// ----------------------------------------------------------------------------
__global__ void __launch_bounds__(SCAN_BLOCK) scan1_kernel() {
    int i = blockIdx.x * SCAN_BLOCK + threadIdx.x;
    int v = (i < N_NODES) ? g_counts[i] : 0;
    __shared__ int sh[32];
    int lane = threadIdx.x & 31, w = threadIdx.x >> 5;
#pragma unroll
    for (int o = 16; o; o >>= 1) v += __shfl_xor_sync(~0u, v, o);
    if (lane == 0) sh[w] = v;
    __syncthreads();
    if (w == 0) {
        int s = sh[lane];
#pragma unroll
        for (int o = 16; o; o >>= 1) s += __shfl_xor_sync(~0u, s, o);
        if (lane == 0) g_blksum[blockIdx.x] = s;
    }
}

__global__ void scan2_kernel() {
    __shared__ int s[64];
    int t = threadIdx.x;
    int v = (t < SCAN_NBLK) ? g_blksum[t] : 0;
    s[t] = v;
    __syncthreads();
#pragma unroll
    for (int o = 1; o < 64; o <<= 1) {
        int u = (t >= o) ? s[t - o] : 0;
        __syncthreads();
        s[t] += u;
        __syncthreads();
    }
    if (t < SCAN_NBLK) g_blkoff[t] = s[t] - v;
    if (t == SCAN_NBLK - 1) g_rowptr[N_NODES] = s[t];
}

__global__ void __launch_bounds__(SCAN_BLOCK) scan3_kernel() {
    int b = blockIdx.x, t = threadIdx.x;
    int i = b * SCAN_BLOCK + t;
    int v = (i < N_NODES) ? g_counts[i] : 0;
    int lane = t & 31, w = t >> 5;
    int inc = v;
#pragma unroll
    for (int o = 1; o < 32; o <<= 1) {
        int u = __shfl_up_sync(~0u, inc, o);
        if (lane >= o) inc += u;
    }
    __shared__ int wsum[32];
    if (lane == 31) wsum[w] = inc;
    __syncthreads();
    if (w == 0) {
        int s = wsum[lane];
#pragma unroll
        for (int o = 1; o < 32; o <<= 1) {
            int u = __shfl_up_sync(~0u, s, o);
            if (lane >= o) s += u;
        }
        wsum[lane] = s;
    }
    __syncthreads();
    int exc = inc - v + (w > 0 ? wsum[w - 1] : 0) + g_blkoff[b];
    if (i < N_NODES) {
        g_rowptr[i] = exc;
        g_cursor[i] = exc;
    }
}

// ----------------------------------------------------------------------------
// 4) fill CSR directly from edge_index (no staging arrays)
// ----------------------------------------------------------------------------
__global__ void fill_kernel(const void* __restrict__ ei, int E) {
    int e = blockIdx.x * blockDim.x + threadIdx.x;
    if (e >= E) return;
    int s, d;
    if (g_is64) {
        const long long* p = (const long long*)ei;
        s = (int)p[e]; d = (int)p[E + e];
    } else {
        const int* p = (const int*)ei;
        s = p[e]; d = p[E + e];
    }
    int pos = atomicAdd(&g_cursor[d], 1);
    g_csr_src[pos] = s;
}

// ----------------------------------------------------------------------------
// GEMM1 fused (3xFP16 HMMA + register prefetch): h1 = x @ W1
// Prefetch next k-tile's global loads into registers during current MMAs.
// ----------------------------------------------------------------------------
__global__ void __launch_bounds__(256) gemm1_fused(const float* __restrict__ A,
                                                   const float* __restrict__ att_s,
                                                   const float* __restrict__ att_d) {
    constexpr int M = N_NODES, K = IN_C;
    constexpr int BM = 128, BN = 128, BK = 32;
    constexpr int KTILES = K / BK;       // 4
    constexpr int SKA = BK + 8;
    __shared__ __half Ah[BM][SKA], Al[BM][SKA];
    __shared__ __half BhT[BN][SKA], BlT[BN][SKA];
    __shared__ float satt_s[BN], satt_d[BN];

    const int tid = threadIdx.x;
    const int lane = tid & 31, warp = tid >> 5;
    const int g = lane >> 2, t = lane & 3;
    const int warp_m = warp & 3;
    const int warp_n = warp >> 2;
    const int block_row = blockIdx.y * BM;
    const int block_col = blockIdx.x * BN;

    if (tid < BN) {
        satt_s[tid] = att_s[block_col + tid];
        satt_d[tid] = att_d[block_col + tid];
    }

    // per-thread load coordinates (iteration-invariant)
    const int a_r  = tid >> 3;           // A: rows tid/8, tid/8+... (4 slots)
    const int a_c4 = tid & 7;
    const int b_n  = tid >> 2;           // B: 2 slots of 64 rows
    const int b_c8 = tid & 3;

    float4 pa[4];
    uint4  pbh[2], pbl[2];

    auto prefetch = [&](int k0) {
#pragma unroll
        for (int it = 0; it < 4; it++) {
            int gr = block_row + a_r + it * 32;
            pa[it] = (gr < M) ? *(const float4*)(A + (size_t)gr * K + k0 + a_c4 * 4)
                              : make_float4(0.f, 0.f, 0.f, 0.f);
        }
#pragma unroll
        for (int it = 0; it < 2; it++) {
            int n = b_n + it * 64;
            pbh[it] = *(const uint4*)&g_w1hT[(size_t)(block_col + n) * K + k0 + b_c8 * 8];
            pbl[it] = *(const uint4*)&g_w1lT[(size_t)(block_col + n) * K + k0 + b_c8 * 8];
        }
    };

    float acc[2][8][4];
#pragma unroll
    for (int mt = 0; mt < 2; mt++)
#pragma unroll
        for (int nt = 0; nt < 8; nt++)
#pragma unroll
            for (int q = 0; q < 4; q++) acc[mt][nt][q] = 0.f;

    prefetch(0);

    for (int kt = 0; kt < KTILES; kt++) {
        // store prefetched tile to smem (split A)
#pragma unroll
        for (int it = 0; it < 4; it++) {
            int r = a_r + it * 32;
            float4 v = pa[it];
            __half h0, l0, h1, l1, h2, l2, h3, l3;
            split_h(v.x, h0, l0); split_h(v.y, h1, l1);
            split_h(v.z, h2, l2); split_h(v.w, h3, l3);
            int c = a_c4 * 4;
            Ah[r][c + 0] = h0; Ah[r][c + 1] = h1; Ah[r][c + 2] = h2; Ah[r][c + 3] = h3;
            Al[r][c + 0] = l0; Al[r][c + 1] = l1; Al[r][c + 2] = l2; Al[r][c + 3] = l3;
        }
#pragma unroll
        for (int it = 0; it < 2; it++) {
            int n = b_n + it * 64;
            *(uint4*)&BhT[n][b_c8 * 8] = pbh[it];
            *(uint4*)&BlT[n][b_c8 * 8] = pbl[it];
        }
        __syncthreads();

        if (kt + 1 < KTILES) prefetch((kt + 1) * BK);   // hide latency under MMAs

#pragma unroll
        for (int ks = 0; ks < 2; ks++) {
            const int kk = ks * 16;
            unsigned ah[2][4], al[2][4];
#pragma unroll
            for (int mt = 0; mt < 2; mt++) {
                int r0 = warp_m * 32 + mt * 16 + g;
                ah[mt][0] = *(const unsigned*)&Ah[r0][kk + 2 * t];
                ah[mt][1] = *(const unsigned*)&Ah[r0 + 8][kk + 2 * t];
                ah[mt][2] = *(const unsigned*)&Ah[r0][kk + 2 * t + 8];
                ah[mt][3] = *(const unsigned*)&Ah[r0 + 8][kk + 2 * t + 8];
                al[mt][0] = *(const unsigned*)&Al[r0][kk + 2 * t];
                al[mt][1] = *(const unsigned*)&Al[r0 + 8][kk + 2 * t];
                al[mt][2] = *(const unsigned*)&Al[r0][kk + 2 * t + 8];
                al[mt][3] = *(const unsigned*)&Al[r0 + 8][kk + 2 * t + 8];
            }
#pragma unroll
            for (int nt = 0; nt < 8; nt++) {
                int n0 = warp_n * 64 + nt * 8 + g;
                unsigned bh[2], bl[2];
                bh[0] = *(const unsigned*)&BhT[n0][kk + 2 * t];
                bh[1] = *(const unsigned*)&BhT[n0][kk + 2 * t + 8];
                bl[0] = *(const unsigned*)&BlT[n0][kk + 2 * t];
                bl[1] = *(const unsigned*)&BlT[n0][kk + 2 * t + 8];
#pragma unroll
                for (int mt = 0; mt < 2; mt++) {
                    mma_f16(acc[mt][nt], ah[mt], bl);
                    mma_f16(acc[mt][nt], al[mt], bh);
                    mma_f16(acc[mt][nt], ah[mt], bh);
                }
            }
        }
        __syncthreads();
    }

    const int head = blockIdx.x * 2 + warp_n;
#pragma unroll
    for (int mt = 0; mt < 2; mt++) {
#pragma unroll
        for (int rr = 0; rr < 2; rr++) {
            int grow = block_row + warp_m * 32 + mt * 16 + g + rr * 8;
            bool valid = grow < M;
            float as_p = 0.f, ad_p = 0.f;
#pragma unroll
            for (int nt = 0; nt < 8; nt++) {
                float v0 = acc[mt][nt][rr * 2 + 0];
                float v1 = acc[mt][nt][rr * 2 + 1];
                int col = warp_n * 64 + nt * 8 + 2 * t;
                as_p += v0 * satt_s[col] + v1 * satt_s[col + 1];
                ad_p += v0 * satt_d[col] + v1 * satt_d[col + 1];
                if (valid) {
                    __nv_fp8x2_storage_t p = __nv_cvt_float2_to_fp8x2(
                        make_float2(v0, v1), __NV_SATFINITE, __NV_E4M3);
                    *(unsigned short*)&g_h1q[(size_t)grow * F1 + block_col + col] =
                        (unsigned short)p;
                }
            }
            as_p += __shfl_xor_sync(0xffffffffu, as_p, 1);
            as_p += __shfl_xor_sync(0xffffffffu, as_p, 2);
            ad_p += __shfl_xor_sync(0xffffffffu, ad_p, 1);
            ad_p += __shfl_xor_sync(0xffffffffu, ad_p, 2);
            if (t == 0 && valid) {
                g_as1[grow * HEADS + head] = as_p;
                g_ad1[grow * HEADS + head] = ad_p;
            }
        }
    }
}

// ----------------------------------------------------------------------------
// GEMM2 fused (2xFP16 HMMA, exact fp16 A, register prefetch): h2 = x2h @ W2
// ----------------------------------------------------------------------------
__global__ void __launch_bounds__(128) gemm2_fused(const float* __restrict__ att_s,
                                                   const float* __restrict__ att_d) {
    constexpr int M = N_NODES, K = F1;
    constexpr int BM = 128, BN = 64, BK = 32;
    constexpr int KTILES = K / BK;       // 8
    constexpr int SKA = BK + 8;
    const __half* A = g_x2h;
    __shared__ __half Ah[BM][SKA];
    __shared__ __half BhT[BN][SKA], BlT[BN][SKA];
    __shared__ float satt_s[BN], satt_d[BN];

    const int tid = threadIdx.x;
    const int lane = tid & 31, warp = tid >> 5;
    const int g = lane >> 2, t = lane & 3;
    const int block_row = blockIdx.y * BM;

    if (tid < BN) {
        satt_s[tid] = att_s[tid];
        satt_d[tid] = att_d[tid];
    }

    const int a_r  = tid >> 2;           // 4 slots of 32 rows
    const int a_c8 = tid & 3;
    const int b_n  = tid >> 2;           // 2 slots of 32 rows (n < 64)
    const int b_c8 = tid & 3;

    uint4 pa[4], pbh[2], pbl[2];

    auto prefetch = [&](int k0) {
#pragma unroll
        for (int it = 0; it < 4; it++) {
            int gr = block_row + a_r + it * 32;
            pa[it] = (gr < M) ? *(const uint4*)(A + (size_t)gr * K + k0 + a_c8 * 8)
                              : make_uint4(0u, 0u, 0u, 0u);
        }
#pragma unroll
        for (int it = 0; it < 2; it++) {
            int n = b_n + it * 32;
            pbh[it] = *(const uint4*)&g_w2hT[(size_t)n * K + k0 + b_c8 * 8];
            pbl[it] = *(const uint4*)&g_w2lT[(size_t)n * K + k0 + b_c8 * 8];
        }
    };

    float acc[2][8][4];
#pragma unroll
    for (int mt = 0; mt < 2; mt++)
#pragma unroll
        for (int nt = 0; nt < 8; nt++)
#pragma unroll
            for (int q = 0; q < 4; q++) acc[mt][nt][q] = 0.f;

    prefetch(0);

    for (int kt = 0; kt < KTILES; kt++) {
#pragma unroll
        for (int it = 0; it < 4; it++)
            *(uint4*)&Ah[a_r + it * 32][a_c8 * 8] = pa[it];
#pragma unroll
        for (int it = 0; it < 2; it++) {
            int n = b_n + it * 32;
            *(uint4*)&BhT[n][b_c8 * 8] = pbh[it];
            *(uint4*)&BlT[n][b_c8 * 8] = pbl[it];
        }
        __syncthreads();

        if (kt + 1 < KTILES) prefetch((kt + 1) * BK);

#pragma unroll
        for (int ks = 0; ks < 2; ks++) {
            const int kk = ks * 16;
            unsigned ah[2][4];
#pragma unroll
            for (int mt = 0; mt < 2; mt++) {
                int r0 = warp * 32 + mt * 16 + g;
                ah[mt][0] = *(const unsigned*)&Ah[r0][kk + 2 * t];
                ah[mt][1] = *(const unsigned*)&Ah[r0 + 8][kk + 2 * t];
                ah[mt][2] = *(const unsigned*)&Ah[r0][kk + 2 * t + 8];
                ah[mt][3] = *(const unsigned*)&Ah[r0 + 8][kk + 2 * t + 8];
            }
#pragma unroll
            for (int nt = 0; nt < 8; nt++) {
                int n0 = nt * 8 + g;
                unsigned bh[2], bl[2];
                bh[0] = *(const unsigned*)&BhT[n0][kk + 2 * t];
                bh[1] = *(const unsigned*)&BhT[n0][kk + 2 * t + 8];
                bl[0] = *(const unsigned*)&BlT[n0][kk + 2 * t];
                bl[1] = *(const unsigned*)&BlT[n0][kk + 2 * t + 8];
#pragma unroll
                for (int mt = 0; mt < 2; mt++) {
                    mma_f16(acc[mt][nt], ah[mt], bl);
                    mma_f16(acc[mt][nt], ah[mt], bh);
                }
            }
        }
        __syncthreads();
    }

#pragma unroll
    for (int mt = 0; mt < 2; mt++) {
#pragma unroll
        for (int rr = 0; rr < 2; rr++) {
            int grow = block_row + warp * 32 + mt * 16 + g + rr * 8;
            bool valid = grow < M;
            float as_p = 0.f, ad_p = 0.f;
#pragma unroll
            for (int nt = 0; nt < 8; nt++) {
                float v0 = acc[mt][nt][rr * 2 + 0];
                float v1 = acc[mt][nt][rr * 2 + 1];
                int col = nt * 8 + 2 * t;
                as_p += v0 * satt_s[col] + v1 * satt_s[col + 1];
                ad_p += v0 * satt_d[col] + v1 * satt_d[col + 1];
                if (valid) {
                    __half2 hv = __floats2half2_rn(v0, v1);
                    *(__half2*)&g_h2h[(size_t)grow * OUT_C + col] = hv;
                }
            }
            as_p += __shfl_xor_sync(0xffffffffu, as_p, 1);
            as_p += __shfl_xor_sync(0xffffffffu, as_p, 2);
            ad_p += __shfl_xor_sync(0xffffffffu, ad_p, 1);
            ad_p += __shfl_xor_sync(0xffffffffu, ad_p, 2);
            if (t == 0 && valid) {
                g_as2[grow] = as_p;
                g_ad2[grow] = ad_p;
            }
        }
    }
}

// ----------------------------------------------------------------------------
// Layer-1 aggregation (PROVEN r10): warp per dst node, single-pass softmax,
// FP8 gathers, fp32 accumulation, fp16 x2 output.
// ----------------------------------------------------------------------------
__global__ void agg1_kernel(const float* __restrict__ b1) {
    int t = threadIdx.x;
    int warp = (blockIdx.x * blockDim.x + t) >> 5;
    if (warp >= N_NODES) return;
    int lane = t & 31;
    int d = warp;
    int head = lane >> 3;

    float ad = g_ad1[d * HEADS + head];
    int beg = g_rowptr[d], end = g_rowptr[d + 1];

    float denom = 1e-16f;
    float acc[8] = {0.f, 0.f, 0.f, 0.f, 0.f, 0.f, 0.f, 0.f};
    for (int i = beg; i < end; i++) {
        int s = g_csr_src[i];
        float w = __expf(lrelu(g_as1[s * HEADS + head] + ad));
        denom += w;
        uint2 u = *(const uint2*)&g_h1q[(size_t)s * F1 + lane * 8];
        float2 f0 = fp8x2_to_float2((unsigned short)(u.x & 0xffffu));
        float2 f1 = fp8x2_to_float2((unsigned short)(u.x >> 16));
        float2 f2 = fp8x2_to_float2((unsigned short)(u.y & 0xffffu));
        float2 f3 = fp8x2_to_float2((unsigned short)(u.y >> 16));
        acc[0] += w * f0.x; acc[1] += w * f0.y;
        acc[2] += w * f1.x; acc[3] += w * f1.y;
        acc[4] += w * f2.x; acc[5] += w * f2.y;
        acc[6] += w * f3.x; acc[7] += w * f3.y;
    }
    {   // self loop
        float w = __expf(lrelu(g_as1[d * HEADS + head] + ad));
        denom += w;
        uint2 u = *(const uint2*)&g_h1q[(size_t)d * F1 + lane * 8];
        float2 f0 = fp8x2_to_float2((unsigned short)(u.x & 0xffffu));
        float2 f1 = fp8x2_to_float2((unsigned short)(u.x >> 16));
        float2 f2 = fp8x2_to_float2((unsigned short)(u.y & 0xffffu));
        float2 f3 = fp8x2_to_float2((unsigned short)(u.y >> 16));
        acc[0] += w * f0.x; acc[1] += w * f0.y;
        acc[2] += w * f1.x; acc[3] += w * f1.y;
        acc[4] += w * f2.x; acc[5] += w * f2.y;
        acc[6] += w * f3.x; acc[7] += w * f3.y;
    }
    float inv = 1.f / denom;
    int cb = lane * 8;
    __half hbuf[8];
#pragma unroll
    for (int j = 0; j < 8; j++)
        hbuf[j] = __float2half(fmaxf(acc[j] * inv + b1[cb + j], 0.f));
    *(uint4*)&g_x2h[(size_t)d * F1 + cb] = *(uint4*)hbuf;
}

// ----------------------------------------------------------------------------
// Layer-2 aggregation (PROVEN r10) + bias + relu + global mean-pool.
// ----------------------------------------------------------------------------
__global__ void agg2_pool_kernel(const float* __restrict__ b2) {
    __shared__ float sp[OUT_C];
    int t = threadIdx.x;
    if (t < OUT_C) sp[t] = 0.f;
    __syncthreads();

    int warp = (blockIdx.x * blockDim.x + t) >> 5;
    int lane = t & 31;
    if (warp < N_NODES) {
        int d = warp;
        float ad = g_ad2[d];
        int beg = g_rowptr[d], end = g_rowptr[d + 1];

        float denom = 1e-16f;
        float a0 = 0.f, a1 = 0.f;
        for (int i = beg; i < end; i++) {
            int s = g_csr_src[i];
            float w = __expf(lrelu(g_as2[s] + ad));
            denom += w;
            a0 += w * __half2float(g_h2h[(size_t)s * OUT_C + lane]);
            a1 += w * __half2float(g_h2h[(size_t)s * OUT_C + 32 + lane]);
        }
        {
            float w = __expf(lrelu(g_as2[d] + ad));
            denom += w;
            a0 += w * __half2float(g_h2h[(size_t)d * OUT_C + lane]);
            a1 += w * __half2float(g_h2h[(size_t)d * OUT_C + 32 + lane]);
        }
        float inv = 1.f / denom;
        float v0 = fmaxf(a0 * inv + b2[lane], 0.f);
        float v1 = fmaxf(a1 * inv + b2[32 + lane], 0.f);
        atomicAdd(&sp[lane], v0);
        atomicAdd(&sp[32 + lane], v1);
    }
    __syncthreads();
    if (t < OUT_C) atomicAdd(&g_pooled[t], sp[t]);
}

// ----------------------------------------------------------------------------
// Final: mean-pool scale, FC to 40 classes, log_softmax
// ----------------------------------------------------------------------------
__global__ void final_kernel(const float* __restrict__ fc_w,
                             const float* __restrict__ fc_b,
                             float* __restrict__ out) {
    __shared__ float p[OUT_C];
    __shared__ float lg[NUM_CLASSES];
    __shared__ float lse_sh;
    int t = threadIdx.x;  // 64 threads
    p[t] = g_pooled[t] * (1.0f / (float)N_NODES);
    __syncthreads();
    if (t < NUM_CLASSES) {
        float s = fc_b[t];
#pragma unroll
        for (int c = 0; c < OUT_C; c++) s += p[c] * fc_w[c * NUM_CLASSES + t];
        lg[t] = s;
    }
    __syncthreads();
    if (t == 0) {
        float mx = lg[0];
        for (int j = 1; j < NUM_CLASSES; j++) mx = fmaxf(mx, lg[j]);
        float se = 0.f;
        for (int j = 0; j < NUM_CLASSES; j++) se += expf(lg[j] - mx);
        lse_sh = mx + logf(se);
    }
    __syncthreads();
    if (t < NUM_CLASSES) out[t] = lg[t] - lse_sh;
}

// ----------------------------------------------------------------------------
// launch: CSR build (side stream) overlaps wsplit+gemm1 (main stream).
// ----------------------------------------------------------------------------
extern "C" void kernel_launch(void* const* d_in, const int* in_sizes, int n_in,
                              void* d_out, int out_size) {
    const float* x      = (const float*)d_in[0];
    const void*  ei     = d_in[1];
    const float* W1     = (const float*)d_in[2];
    const float* att_s1 = (const float*)d_in[3];
    const float* att_d1 = (const float*)d_in[4];
    const float* b1     = (const float*)d_in[5];
    const float* W2     = (const float*)d_in[6];
    const float* att_s2 = (const float*)d_in[7];
    const float* att_d2 = (const float*)d_in[8];
    const float* b2     = (const float*)d_in[9];
    const float* fc_w   = (const float*)d_in[10];
    const float* fc_b   = (const float*)d_in[11];
    float* out = (float*)d_out;

    int E = in_sizes[1] / 2;
    if (E > E_MAX) E = E_MAX;

    const int WARPS_PER_BLOCK = 8;
    const int nodeBlocks = (N_NODES + WARPS_PER_BLOCK - 1) / WARPS_PER_BLOCK;
    const int mBlocks = (N_NODES + 127) / 128;

    static cudaStream_t s_side = nullptr;
    static cudaEvent_t  ev_fork = nullptr, ev_join = nullptr;
    if (s_side == nullptr) {
        cudaStreamCreateWithFlags(&s_side, cudaStreamNonBlocking);
        cudaEventCreateWithFlags(&ev_fork, cudaEventDisableTiming);
        cudaEventCreateWithFlags(&ev_join, cudaEventDisableTiming);
    }

    // Fork: CSR-build chain on side stream
    cudaEventRecord(ev_fork, 0);
    cudaStreamWaitEvent(s_side, ev_fork, 0);

    init_detect_kernel<<<(N_NODES + 256) / 256, 256, 0, s_side>>>((const int*)ei);
    count_kernel<<<(E + 255) / 256, 256, 0, s_side>>>(ei, E);
    scan1_kernel<<<SCAN_NBLK, SCAN_BLOCK, 0, s_side>>>();
    scan2_kernel<<<1, 64, 0, s_side>>>();
    scan3_kernel<<<SCAN_NBLK, SCAN_BLOCK, 0, s_side>>>();
    fill_kernel<<<(E + 255) / 256, 256, 0, s_side>>>(ei, E);
    cudaEventRecord(ev_join, s_side);

    // Concurrent on main stream: weight split + layer-1 GEMM
    wsplit_kernel<<<(IN_C * F1 + 255) / 256, 256>>>(W1, W2);
    gemm1_fused<<<dim3(F1 / 128, mBlocks), 256>>>(x, att_s1, att_d1);

    // Join: agg1 needs both CSR and gemm1
    cudaStreamWaitEvent(0, ev_join, 0);

    agg1_kernel<<<nodeBlocks, 256>>>(b1);
    gemm2_fused<<<dim3(1, mBlocks), 128>>>(att_s2, att_d2);
    agg2_pool_kernel<<<nodeBlocks, 256>>>(b2);
    final_kernel<<<1, 64>>>(fc_w, fc_b, out);
}

// round 15
// speedup vs baseline: 1.1118x; 1.0826x over previous
#include <cuda_runtime.h>
#include <cuda_bf16.h>
#include <cuda_fp16.h>
#include <cuda_fp8.h>
#include <math.h>

// Problem constants (fixed by the reference)
#define N_NODES 50000
#define E_MAX   800000
#define IN_C    128
#define HID     64
#define HEADS   4
#define F1      (HEADS*HID)   // 256
#define OUT_C   64
#define NUM_CLASSES 40

#define SCAN_BLOCK 1024
#define SCAN_NBLK  ((N_NODES + SCAN_BLOCK - 1) / SCAN_BLOCK)   // 49

// ----------------------------------------------------------------------------
// Scratch (device globals: allocation-free per harness rules)
// ----------------------------------------------------------------------------
__device__ unsigned char g_h1q[(size_t)N_NODES * F1];  // layer-1 features, fp8 e4m3
__device__ __half g_x2h[(size_t)N_NODES * F1];         // layer-1 GAT output, fp16
__device__ __half g_h2h[(size_t)N_NODES * OUT_C];      // layer-2 features, fp16
__device__ __half g_w1hT[(size_t)F1 * IN_C];           // W1^T hi  [n][k]
__device__ __half g_w1lT[(size_t)F1 * IN_C];           // W1^T lo
__device__ __half g_w2hT[(size_t)OUT_C * F1];          // W2^T hi
__device__ __half g_w2lT[(size_t)OUT_C * F1];          // W2^T lo
__device__ float  g_as1[N_NODES * HEADS];
__device__ float  g_ad1[N_NODES * HEADS];
__device__ float  g_as2[N_NODES];
__device__ float  g_ad2[N_NODES];
__device__ int    g_counts[N_NODES + 1];
__device__ int    g_rowptr[N_NODES + 1];
__device__ int    g_cursor[N_NODES];
__device__ int    g_csr_src[E_MAX];
__device__ int    g_blksum[SCAN_NBLK];
__device__ int    g_blkoff[SCAN_NBLK];
__device__ float  g_pooled[OUT_C];
__device__ int    g_is64;

__device__ __forceinline__ float lrelu(float v) { return v > 0.f ? v : 0.2f * v; }

__device__ __forceinline__ void split_h(float v, __half& hi, __half& lo) {
    hi = __float2half(v);
    lo = __float2half(v - __half2float(hi));
}

__device__ __forceinline__ float2 fp8x2_to_float2(unsigned short v) {
    __half2_raw hr = __nv_cvt_fp8x2_to_halfraw2((__nv_fp8x2_storage_t)v, __NV_E4M3);
    return __half22float2(*reinterpret_cast<__half2*>(&hr));
}

// m16n8k16 fp16 MMA, fp32 accumulate
__device__ __forceinline__ void mma_f16(float* c, const unsigned* a, const unsigned* b) {
    asm volatile(
        "mma.sync.aligned.m16n8k16.row.col.f32.f16.f16.f32 "
        "{%0,%1,%2,%3}, {%4,%5,%6,%7}, {%8,%9}, {%0,%1,%2,%3};\n"
        : "+f"(c[0]), "+f"(c[1]), "+f"(c[2]), "+f"(c[3])
        : "r"(a[0]), "r"(a[1]), "r"(a[2]), "r"(a[3]), "r"(b[0]), "r"(b[1]));
}

// ----------------------------------------------------------------------------
// W pre-split + transpose: W1[k][n] -> w1{h,l}T[n][k]; W2 likewise. Tiny.
// ----------------------------------------------------------------------------
__global__ void wsplit_kernel(const float* __restrict__ W1,
                              const float* __restrict__ W2) {
    int i = blockIdx.x * blockDim.x + threadIdx.x;
    if (i < IN_C * F1) {
        int k = i / F1, n = i % F1;
        __half h, l; split_h(W1[i], h, l);
        g_w1hT[(size_t)n * IN_C + k] = h;
        g_w1lT[(size_t)n * IN_C + k] = l;
    }
    if (i < F1 * OUT_C) {
        int k = i / OUT_C, n = i % OUT_C;
        __half h, l; split_h(W2[i], h, l);
        g_w2hT[(size_t)n * F1 + k] = h;
        g_w2lT[(size_t)n * F1 + k] = l;
    }
}

// ----------------------------------------------------------------------------
// 0+1) init (zero counts + pooled) and int64/int32 detection, one launch
// ----------------------------------------------------------------------------
__global__ void init_detect_kernel(const int* __restrict__ ei) {
    int i = blockIdx.x * blockDim.x + threadIdx.x;
    if (i < N_NODES + 1) g_counts[i] = 0;
    if (i < OUT_C)       g_pooled[i] = 0.f;
    if (blockIdx.x == 0) {
        __shared__ int any;
        if (threadIdx.x == 0) any = 0;
        __syncthreads();
        for (int j = threadIdx.x; j < 4096; j += blockDim.x) {
            if (ei[2 * j + 1] != 0) any = 1;
        }
        __syncthreads();
        if (threadIdx.x == 0) g_is64 = (any == 0) ? 1 : 0;
    }
}

// ----------------------------------------------------------------------------
// 2) count in-degrees (reads edge_index directly; no staging arrays)
// ----------------------------------------------------------------------------
__global__ void count_kernel(const void* __restrict__ ei, int E) {
    int e = blockIdx.x * blockDim.x + threadIdx.x;
    if (e >= E) return;
    int d;
    if (g_is64) d = (int)((const long long*)ei)[E + e];
    else        d = ((const int*)ei)[E + e];
    atomicAdd(&g_counts[d], 1);
}

// ----------------------------------------------------------------------------
// 3) parallel exclusive scan of g_counts -> g_rowptr / g_cursor  (PROVEN r4)
// ----------------------------------------------------------------------------
__global__ void __launch_bounds__(SCAN_BLOCK) scan1_kernel() {
    int i = blockIdx.x * SCAN_BLOCK + threadIdx.x;
    int v = (i < N_NODES) ? g_counts[i] : 0;
    __shared__ int sh[32];
    int lane = threadIdx.x & 31, w = threadIdx.x >> 5;
#pragma unroll
    for (int o = 16; o; o >>= 1) v += __shfl_xor_sync(~0u, v, o);
    if (lane == 0) sh[w] = v;
    __syncthreads();
    if (w == 0) {
        int s = sh[lane];
#pragma unroll
        for (int o = 16; o; o >>= 1) s += __shfl_xor_sync(~0u, s, o);
        if (lane == 0) g_blksum[blockIdx.x] = s;
    }
}

__global__ void scan2_kernel() {
    __shared__ int s[64];
    int t = threadIdx.x;
    int v = (t < SCAN_NBLK) ? g_blksum[t] : 0;
    s[t] = v;
    __syncthreads();
#pragma unroll
    for (int o = 1; o < 64; o <<= 1) {
        int u = (t >= o) ? s[t - o] : 0;
        __syncthreads();
        s[t] += u;
        __syncthreads();
    }
    if (t < SCAN_NBLK) g_blkoff[t] = s[t] - v;
    if (t == SCAN_NBLK - 1) g_rowptr[N_NODES] = s[t];
}

__global__ void __launch_bounds__(SCAN_BLOCK) scan3_kernel() {
    int b = blockIdx.x, t = threadIdx.x;
    int i = b * SCAN_BLOCK + t;
    int v = (i < N_NODES) ? g_counts[i] : 0;
    int lane = t & 31, w = t >> 5;
    int inc = v;
#pragma unroll
    for (int o = 1; o < 32; o <<= 1) {
        int u = __shfl_up_sync(~0u, inc, o);
        if (lane >= o) inc += u;
    }
    __shared__ int wsum[32];
    if (lane == 31) wsum[w] = inc;
    __syncthreads();
    if (w == 0) {
        int s = wsum[lane];
#pragma unroll
        for (int o = 1; o < 32; o <<= 1) {
            int u = __shfl_up_sync(~0u, s, o);
            if (lane >= o) s += u;
        }
        wsum[lane] = s;
    }
    __syncthreads();
    int exc = inc - v + (w > 0 ? wsum[w - 1] : 0) + g_blkoff[b];
    if (i < N_NODES) {
        g_rowptr[i] = exc;
        g_cursor[i] = exc;
    }
}

// ----------------------------------------------------------------------------
// 4) fill CSR directly from edge_index (no staging arrays)
// ----------------------------------------------------------------------------
__global__ void fill_kernel(const void* __restrict__ ei, int E) {
    int e = blockIdx.x * blockDim.x + threadIdx.x;
    if (e >= E) return;
    int s, d;
    if (g_is64) {
        const long long* p = (const long long*)ei;
        s = (int)p[e]; d = (int)p[E + e];
    } else {
        const int* p = (const int*)ei;
        s = p[e]; d = p[E + e];
    }
    int pos = atomicAdd(&g_cursor[d], 1);
    g_csr_src[pos] = s;
}

// ----------------------------------------------------------------------------
// GEMM1 fused (2xFP16 HMMA, fp16 A / split B): h1 = x @ W1
// A rounded to fp16 (per-entry, per-node errors -> decorrelated); B = W1 kept
// at fp32-class precision via hi/lo split. r10 loading structure, no prefetch.
// ----------------------------------------------------------------------------
__global__ void __launch_bounds__(256) gemm1_fused(const float* __restrict__ A,
                                                   const float* __restrict__ att_s,
                                                   const float* __restrict__ att_d) {
    constexpr int M = N_NODES, K = IN_C;
    constexpr int BM = 128, BN = 128, BK = 32;
    constexpr int SKA = BK + 8;
    __shared__ __half Ah[BM][SKA];
    __shared__ __half BhT[BN][SKA], BlT[BN][SKA];
    __shared__ float satt_s[BN], satt_d[BN];

    const int tid = threadIdx.x;
    const int lane = tid & 31, warp = tid >> 5;
    const int g = lane >> 2, t = lane & 3;
    const int warp_m = warp & 3;
    const int warp_n = warp >> 2;
    const int block_row = blockIdx.y * BM;
    const int block_col = blockIdx.x * BN;

    if (tid < BN) {
        satt_s[tid] = att_s[block_col + tid];
        satt_d[tid] = att_d[block_col + tid];
    }

    float acc[2][8][4];
#pragma unroll
    for (int mt = 0; mt < 2; mt++)
#pragma unroll
        for (int nt = 0; nt < 8; nt++)
#pragma unroll
            for (int q = 0; q < 4; q++) acc[mt][nt][q] = 0.f;

    for (int k0 = 0; k0 < K; k0 += BK) {
        // A tile 128x32 fp32 -> fp16 (no split)
#pragma unroll
        for (int it = 0; it < 4; it++) {
            int idx = tid + it * 256;
            int r  = idx >> 3;
            int c4 = idx & 7;
            int gr = block_row + r;
            float4 v = make_float4(0.f, 0.f, 0.f, 0.f);
            if (gr < M) v = *(const float4*)(A + (size_t)gr * K + k0 + c4 * 4);
            int c = c4 * 4;
            Ah[r][c + 0] = __float2half(v.x);
            Ah[r][c + 1] = __float2half(v.y);
            Ah[r][c + 2] = __float2half(v.z);
            Ah[r][c + 3] = __float2half(v.w);
        }
        // B tiles: pre-split, pre-transposed -> pure uint4 copies
#pragma unroll
        for (int it = 0; it < 2; it++) {
            int idx = tid + it * 256;
            int n = idx >> 2, c8 = idx & 3;
            *(uint4*)&BhT[n][c8 * 8] =
                *(const uint4*)&g_w1hT[(size_t)(block_col + n) * K + k0 + c8 * 8];
        }
#pragma unroll
        for (int it = 0; it < 2; it++) {
            int idx = tid + it * 256;
            int n = idx >> 2, c8 = idx & 3;
            *(uint4*)&BlT[n][c8 * 8] =
                *(const uint4*)&g_w1lT[(size_t)(block_col + n) * K + k0 + c8 * 8];
        }
        __syncthreads();
#pragma unroll
        for (int ks = 0; ks < 2; ks++) {
            const int kk = ks * 16;
            unsigned ah[2][4];
#pragma unroll
            for (int mt = 0; mt < 2; mt++) {
                int r0 = warp_m * 32 + mt * 16 + g;
                ah[mt][0] = *(const unsigned*)&Ah[r0][kk + 2 * t];
                ah[mt][1] = *(const unsigned*)&Ah[r0 + 8][kk + 2 * t];
                ah[mt][2] = *(const unsigned*)&Ah[r0][kk + 2 * t + 8];
                ah[mt][3] = *(const unsigned*)&Ah[r0 + 8][kk + 2 * t + 8];
            }
#pragma unroll
            for (int nt = 0; nt < 8; nt++) {
                int n0 = warp_n * 64 + nt * 8 + g;
                unsigned bh[2], bl[2];
                bh[0] = *(const unsigned*)&BhT[n0][kk + 2 * t];
                bh[1] = *(const unsigned*)&BhT[n0][kk + 2 * t + 8];
                bl[0] = *(const unsigned*)&BlT[n0][kk + 2 * t];
                bl[1] = *(const unsigned*)&BlT[n0][kk + 2 * t + 8];
#pragma unroll
                for (int mt = 0; mt < 2; mt++) {
                    mma_f16(acc[mt][nt], ah[mt], bl);   // small term first
                    mma_f16(acc[mt][nt], ah[mt], bh);
                }
            }
        }
        __syncthreads();
    }

    const int head = blockIdx.x * 2 + warp_n;
#pragma unroll
    for (int mt = 0; mt < 2; mt++) {
#pragma unroll
        for (int rr = 0; rr < 2; rr++) {
            int grow = block_row + warp_m * 32 + mt * 16 + g + rr * 8;
            bool valid = grow < M;
            float as_p = 0.f, ad_p = 0.f;
#pragma unroll
            for (int nt = 0; nt < 8; nt++) {
                float v0 = acc[mt][nt][rr * 2 + 0];
                float v1 = acc[mt][nt][rr * 2 + 1];
                int col = warp_n * 64 + nt * 8 + 2 * t;
                as_p += v0 * satt_s[col] + v1 * satt_s[col + 1];
                ad_p += v0 * satt_d[col] + v1 * satt_d[col + 1];
                if (valid) {
                    __nv_fp8x2_storage_t p = __nv_cvt_float2_to_fp8x2(
                        make_float2(v0, v1), __NV_SATFINITE, __NV_E4M3);
                    *(unsigned short*)&g_h1q[(size_t)grow * F1 + block_col + col] =
                        (unsigned short)p;
                }
            }
            as_p += __shfl_xor_sync(0xffffffffu, as_p, 1);
            as_p += __shfl_xor_sync(0xffffffffu, as_p, 2);
            ad_p += __shfl_xor_sync(0xffffffffu, ad_p, 1);
            ad_p += __shfl_xor_sync(0xffffffffu, ad_p, 2);
            if (t == 0 && valid) {
                g_as1[grow * HEADS + head] = as_p;
                g_ad1[grow * HEADS + head] = ad_p;
            }
        }
    }
}

// ----------------------------------------------------------------------------
// GEMM2 fused (2xFP16 HMMA, exact fp16 A): h2 = x2h @ W2  (PROVEN r10, exact)
// ----------------------------------------------------------------------------
__global__ void __launch_bounds__(128) gemm2_fused(const float* __restrict__ att_s,
                                                   const float* __restrict__ att_d) {
    constexpr int M = N_NODES, K = F1;
    constexpr int BM = 128, BN = 64, BK = 32;
    constexpr int SKA = BK + 8;
    const __half* A = g_x2h;
    __shared__ __half Ah[BM][SKA];
    __shared__ __half BhT[BN][SKA], BlT[BN][SKA];
    __shared__ float satt_s[BN], satt_d[BN];

    const int tid = threadIdx.x;
    const int lane = tid & 31, warp = tid >> 5;
    const int g = lane >> 2, t = lane & 3;
    const int block_row = blockIdx.y * BM;

    if (tid < BN) {
        satt_s[tid] = att_s[tid];
        satt_d[tid] = att_d[tid];
    }

    float acc[2][8][4];
#pragma unroll
    for (int mt = 0; mt < 2; mt++)
#pragma unroll
        for (int nt = 0; nt < 8; nt++)
#pragma unroll
            for (int q = 0; q < 4; q++) acc[mt][nt][q] = 0.f;

    for (int k0 = 0; k0 < K; k0 += BK) {
#pragma unroll
        for (int it = 0; it < 4; it++) {
            int idx = tid + it * 128;
            int r  = idx >> 2;
            int c8 = idx & 3;
            int gr = block_row + r;
            uint4 v = make_uint4(0u, 0u, 0u, 0u);
            if (gr < M) v = *(const uint4*)(A + (size_t)gr * K + k0 + c8 * 8);
            *(uint4*)&Ah[r][c8 * 8] = v;
        }
#pragma unroll
        for (int it = 0; it < 2; it++) {
            int idx = tid + it * 128;
            int n = idx >> 2, c8 = idx & 3;
            *(uint4*)&BhT[n][c8 * 8] =
                *(const uint4*)&g_w2hT[(size_t)n * K + k0 + c8 * 8];
        }
#pragma unroll
        for (int it = 0; it < 2; it++) {
            int idx = tid + it * 128;
            int n = idx >> 2, c8 = idx & 3;
            *(uint4*)&BlT[n][c8 * 8] =
                *(const uint4*)&g_w2lT[(size_t)n * K + k0 + c8 * 8];
        }
        __syncthreads();
#pragma unroll
        for (int ks = 0; ks < 2; ks++) {
            const int kk = ks * 16;
            unsigned ah[2][4];
#pragma unroll
            for (int mt = 0; mt < 2; mt++) {
                int r0 = warp * 32 + mt * 16 + g;
                ah[mt][0] = *(const unsigned*)&Ah[r0][kk + 2 * t];
                ah[mt][1] = *(const unsigned*)&Ah[r0 + 8][kk + 2 * t];
                ah[mt][2] = *(const unsigned*)&Ah[r0][kk + 2 * t + 8];
                ah[mt][3] = *(const unsigned*)&Ah[r0 + 8][kk + 2 * t + 8];
            }
#pragma unroll
            for (int nt = 0; nt < 8; nt++) {
                int n0 = nt * 8 + g;
                unsigned bh[2], bl[2];
                bh[0] = *(const unsigned*)&BhT[n0][kk + 2 * t];
                bh[1] = *(const unsigned*)&BhT[n0][kk + 2 * t + 8];
                bl[0] = *(const unsigned*)&BlT[n0][kk + 2 * t];
                bl[1] = *(const unsigned*)&BlT[n0][kk + 2 * t + 8];
#pragma unroll
                for (int mt = 0; mt < 2; mt++) {
                    mma_f16(acc[mt][nt], ah[mt], bl);
                    mma_f16(acc[mt][nt], ah[mt], bh);
                }
            }
        }
        __syncthreads();
    }

#pragma unroll
    for (int mt = 0; mt < 2; mt++) {
#pragma unroll
        for (int rr = 0; rr < 2; rr++) {
            int grow = block_row + warp * 32 + mt * 16 + g + rr * 8;
            bool valid = grow < M;
            float as_p = 0.f, ad_p = 0.f;
#pragma unroll
            for (int nt = 0; nt < 8; nt++) {
                float v0 = acc[mt][nt][rr * 2 + 0];
                float v1 = acc[mt][nt][rr * 2 + 1];
                int col = nt * 8 + 2 * t;
                as_p += v0 * satt_s[col] + v1 * satt_s[col + 1];
                ad_p += v0 * satt_d[col] + v1 * satt_d[col + 1];
                if (valid) {
                    __half2 hv = __floats2half2_rn(v0, v1);
                    *(__half2*)&g_h2h[(size_t)grow * OUT_C + col] = hv;
                }
            }
            as_p += __shfl_xor_sync(0xffffffffu, as_p, 1);
            as_p += __shfl_xor_sync(0xffffffffu, as_p, 2);
            ad_p += __shfl_xor_sync(0xffffffffu, ad_p, 1);
            ad_p += __shfl_xor_sync(0xffffffffu, ad_p, 2);
            if (t == 0 && valid) {
                g_as2[grow] = as_p;
                g_ad2[grow] = ad_p;
            }
        }
    }
}

// ----------------------------------------------------------------------------
// Layer-1 aggregation (PROVEN r10): warp per dst node, single-pass softmax,
// FP8 gathers, fp32 accumulation, fp16 x2 output.
// ----------------------------------------------------------------------------
__global__ void agg1_kernel(const float* __restrict__ b1) {
    int t = threadIdx.x;
    int warp = (blockIdx.x * blockDim.x + t) >> 5;
    if (warp >= N_NODES) return;
    int lane = t & 31;
    int d = warp;
    int head = lane >> 3;

    float ad = g_ad1[d * HEADS + head];
    int beg = g_rowptr[d], end = g_rowptr[d + 1];

    float denom = 1e-16f;
    float acc[8] = {0.f, 0.f, 0.f, 0.f, 0.f, 0.f, 0.f, 0.f};
    for (int i = beg; i < end; i++) {
        int s = g_csr_src[i];
        float w = __expf(lrelu(g_as1[s * HEADS + head] + ad));
        denom += w;
        uint2 u = *(const uint2*)&g_h1q[(size_t)s * F1 + lane * 8];
        float2 f0 = fp8x2_to_float2((unsigned short)(u.x & 0xffffu));
        float2 f1 = fp8x2_to_float2((unsigned short)(u.x >> 16));
        float2 f2 = fp8x2_to_float2((unsigned short)(u.y & 0xffffu));
        float2 f3 = fp8x2_to_float2((unsigned short)(u.y >> 16));
        acc[0] += w * f0.x; acc[1] += w * f0.y;
        acc[2] += w * f1.x; acc[3] += w * f1.y;
        acc[4] += w * f2.x; acc[5] += w * f2.y;
        acc[6] += w * f3.x; acc[7] += w * f3.y;
    }
    {   // self loop
        float w = __expf(lrelu(g_as1[d * HEADS + head] + ad));
        denom += w;
        uint2 u = *(const uint2*)&g_h1q[(size_t)d * F1 + lane * 8];
        float2 f0 = fp8x2_to_float2((unsigned short)(u.x & 0xffffu));
        float2 f1 = fp8x2_to_float2((unsigned short)(u.x >> 16));
        float2 f2 = fp8x2_to_float2((unsigned short)(u.y & 0xffffu));
        float2 f3 = fp8x2_to_float2((unsigned short)(u.y >> 16));
        acc[0] += w * f0.x; acc[1] += w * f0.y;
        acc[2] += w * f1.x; acc[3] += w * f1.y;
        acc[4] += w * f2.x; acc[5] += w * f2.y;
        acc[6] += w * f3.x; acc[7] += w * f3.y;
    }
    float inv = 1.f / denom;
    int cb = lane * 8;
    __half hbuf[8];
#pragma unroll
    for (int j = 0; j < 8; j++)
        hbuf[j] = __float2half(fmaxf(acc[j] * inv + b1[cb + j], 0.f));
    *(uint4*)&g_x2h[(size_t)d * F1 + cb] = *(uint4*)hbuf;
}

// ----------------------------------------------------------------------------
// Layer-2 aggregation (PROVEN r10) + bias + relu + global mean-pool.
// ----------------------------------------------------------------------------
__global__ void agg2_pool_kernel(const float* __restrict__ b2) {
    __shared__ float sp[OUT_C];
    int t = threadIdx.x;
    if (t < OUT_C) sp[t] = 0.f;
    __syncthreads();

    int warp = (blockIdx.x * blockDim.x + t) >> 5;
    int lane = t & 31;
    if (warp < N_NODES) {
        int d = warp;
        float ad = g_ad2[d];
        int beg = g_rowptr[d], end = g_rowptr[d + 1];

        float denom = 1e-16f;
        float a0 = 0.f, a1 = 0.f;
        for (int i = beg; i < end; i++) {
            int s = g_csr_src[i];
            float w = __expf(lrelu(g_as2[s] + ad));
            denom += w;
            a0 += w * __half2float(g_h2h[(size_t)s * OUT_C + lane]);
            a1 += w * __half2float(g_h2h[(size_t)s * OUT_C + 32 + lane]);
        }
        {
            float w = __expf(lrelu(g_as2[d] + ad));
            denom += w;
            a0 += w * __half2float(g_h2h[(size_t)d * OUT_C + lane]);
            a1 += w * __half2float(g_h2h[(size_t)d * OUT_C + 32 + lane]);
        }
        float inv = 1.f / denom;
        float v0 = fmaxf(a0 * inv + b2[lane], 0.f);
        float v1 = fmaxf(a1 * inv + b2[32 + lane], 0.f);
        atomicAdd(&sp[lane], v0);
        atomicAdd(&sp[32 + lane], v1);
    }
    __syncthreads();
    if (t < OUT_C) atomicAdd(&g_pooled[t], sp[t]);
}

// ----------------------------------------------------------------------------
// Final: mean-pool scale, FC to 40 classes, log_softmax
// ----------------------------------------------------------------------------
__global__ void final_kernel(const float* __restrict__ fc_w,
                             const float* __restrict__ fc_b,
                             float* __restrict__ out) {
    __shared__ float p[OUT_C];
    __shared__ float lg[NUM_CLASSES];
    __shared__ float lse_sh;
    int t = threadIdx.x;  // 64 threads
    p[t] = g_pooled[t] * (1.0f / (float)N_NODES);
    __syncthreads();
    if (t < NUM_CLASSES) {
        float s = fc_b[t];
#pragma unroll
        for (int c = 0; c < OUT_C; c++) s += p[c] * fc_w[c * NUM_CLASSES + t];
        lg[t] = s;
    }
    __syncthreads();
    if (t == 0) {
        float mx = lg[0];
        for (int j = 1; j < NUM_CLASSES; j++) mx = fmaxf(mx, lg[j]);
        float se = 0.f;
        for (int j = 0; j < NUM_CLASSES; j++) se += expf(lg[j] - mx);
        lse_sh = mx + logf(se);
    }
    __syncthreads();
    if (t < NUM_CLASSES) out[t] = lg[t] - lse_sh;
}

// ----------------------------------------------------------------------------
// launch: CSR build (side stream) overlaps wsplit+gemm1 (main stream).
// ----------------------------------------------------------------------------
extern "C" void kernel_launch(void* const* d_in, const int* in_sizes, int n_in,
                              void* d_out, int out_size) {
    const float* x      = (const float*)d_in[0];
    const void*  ei     = d_in[1];
    const float* W1     = (const float*)d_in[2];
    const float* att_s1 = (const float*)d_in[3];
    const float* att_d1 = (const float*)d_in[4];
    const float* b1     = (const float*)d_in[5];
    const float* W2     = (const float*)d_in[6];
    const float* att_s2 = (const float*)d_in[7];
    const float* att_d2 = (const float*)d_in[8];
    const float* b2     = (const float*)d_in[9];
    const float* fc_w   = (const float*)d_in[10];
    const float* fc_b   = (const float*)d_in[11];
    float* out = (float*)d_out;

    int E = in_sizes[1] / 2;
    if (E > E_MAX) E = E_MAX;

    const int WARPS_PER_BLOCK = 8;
    const int nodeBlocks = (N_NODES + WARPS_PER_BLOCK - 1) / WARPS_PER_BLOCK;
    const int mBlocks = (N_NODES + 127) / 128;

    static cudaStream_t s_side = nullptr;
    static cudaEvent_t  ev_fork = nullptr, ev_join = nullptr;
    if (s_side == nullptr) {
        cudaStreamCreateWithFlags(&s_side, cudaStreamNonBlocking);
        cudaEventCreateWithFlags(&ev_fork, cudaEventDisableTiming);
        cudaEventCreateWithFlags(&ev_join, cudaEventDisableTiming);
    }

    // Fork: CSR-build chain on side stream
    cudaEventRecord(ev_fork, 0);
    cudaStreamWaitEvent(s_side, ev_fork, 0);

    init_detect_kernel<<<(N_NODES + 256) / 256, 256, 0, s_side>>>((const int*)ei);
    count_kernel<<<(E + 255) / 256, 256, 0, s_side>>>(ei, E);
    scan1_kernel<<<SCAN_NBLK, SCAN_BLOCK, 0, s_side>>>();
    scan2_kernel<<<1, 64, 0, s_side>>>();
    scan3_kernel<<<SCAN_NBLK, SCAN_BLOCK, 0, s_side>>>();
    fill_kernel<<<(E + 255) / 256, 256, 0, s_side>>>(ei, E);
    cudaEventRecord(ev_join, s_side);

    // Concurrent on main stream: weight split + layer-1 GEMM
    wsplit_kernel<<<(IN_C * F1 + 255) / 256, 256>>>(W1, W2);
    gemm1_fused<<<dim3(F1 / 128, mBlocks), 256>>>(x, att_s1, att_d1);

    // Join: agg1 needs both CSR and gemm1
    cudaStreamWaitEvent(0, ev_join, 0);

    agg1_kernel<<<nodeBlocks, 256>>>(b1);
    gemm2_fused<<<dim3(1, mBlocks), 128>>>(att_s2, att_d2);
    agg2_pool_kernel<<<nodeBlocks, 256>>>(b2);
    final_kernel<<<1, 64>>>(fc_w, fc_b, out);
}

// round 16
// speedup vs baseline: 1.1129x; 1.0010x over previous
#include <cuda_runtime.h>
#include <cuda_bf16.h>
#include <cuda_fp16.h>
#include <cuda_fp8.h>
#include <math.h>

// Problem constants (fixed by the reference)
#define N_NODES 50000
#define E_MAX   800000
#define IN_C    128
#define HID     64
#define HEADS   4
#define F1      (HEADS*HID)   // 256
#define OUT_C   64
#define NUM_CLASSES 40

#define SCAN_BLOCK 1024
#define SCAN_NBLK  ((N_NODES + SCAN_BLOCK - 1) / SCAN_BLOCK)   // 49

// ----------------------------------------------------------------------------
// Scratch (device globals: allocation-free per harness rules)
// ----------------------------------------------------------------------------
__device__ unsigned char g_h1q[(size_t)N_NODES * F1];   // layer-1 features, fp8 e4m3
__device__ __half g_x2h[(size_t)N_NODES * F1];          // layer-1 GAT output, fp16
__device__ unsigned char g_h2q[(size_t)N_NODES * OUT_C];// layer-2 features, fp8 e4m3
__device__ __half g_w1hT[(size_t)F1 * IN_C];            // W1^T hi  [n][k]
__device__ __half g_w1lT[(size_t)F1 * IN_C];            // W1^T lo
__device__ __half g_w2hT[(size_t)OUT_C * F1];           // W2^T hi
__device__ __half g_w2lT[(size_t)OUT_C * F1];           // W2^T lo
__device__ float  g_as1[N_NODES * HEADS];
__device__ float  g_ad1[N_NODES * HEADS];
__device__ float  g_as2[N_NODES];
__device__ float  g_ad2[N_NODES];
__device__ int    g_counts[N_NODES + 1];
__device__ int    g_rowptr[N_NODES + 1];
__device__ int    g_cursor[N_NODES];
__device__ int    g_csr_src[E_MAX];
__device__ int    g_blksum[SCAN_NBLK];
__device__ int    g_blkoff[SCAN_NBLK];
__device__ float  g_pooled[OUT_C];
__device__ int    g_is64;

__device__ __forceinline__ float lrelu(float v) { return v > 0.f ? v : 0.2f * v; }

__device__ __forceinline__ void split_h(float v, __half& hi, __half& lo) {
    hi = __float2half(v);
    lo = __float2half(v - __half2float(hi));
}

__device__ __forceinline__ float2 fp8x2_to_float2(unsigned short v) {
    __half2_raw hr = __nv_cvt_fp8x2_to_halfraw2((__nv_fp8x2_storage_t)v, __NV_E4M3);
    return __half22float2(*reinterpret_cast<__half2*>(&hr));
}

// m16n8k16 fp16 MMA, fp32 accumulate
__device__ __forceinline__ void mma_f16(float* c, const unsigned* a, const unsigned* b) {
    asm volatile(
        "mma.sync.aligned.m16n8k16.row.col.f32.f16.f16.f32 "
        "{%0,%1,%2,%3}, {%4,%5,%6,%7}, {%8,%9}, {%0,%1,%2,%3};\n"
        : "+f"(c[0]), "+f"(c[1]), "+f"(c[2]), "+f"(c[3])
        : "r"(a[0]), "r"(a[1]), "r"(a[2]), "r"(a[3]), "r"(b[0]), "r"(b[1]));
}

// ----------------------------------------------------------------------------
// W pre-split + transpose: W1[k][n] -> w1{h,l}T[n][k]; W2 likewise. Tiny.
// ----------------------------------------------------------------------------
__global__ void wsplit_kernel(const float* __restrict__ W1,
                              const float* __restrict__ W2) {
    int i = blockIdx.x * blockDim.x + threadIdx.x;
    if (i < IN_C * F1) {
        int k = i / F1, n = i % F1;
        __half h, l; split_h(W1[i], h, l);
        g_w1hT[(size_t)n * IN_C + k] = h;
        g_w1lT[(size_t)n * IN_C + k] = l;
    }
    if (i < F1 * OUT_C) {
        int k = i / OUT_C, n = i % OUT_C;
        __half h, l; split_h(W2[i], h, l);
        g_w2hT[(size_t)n * F1 + k] = h;
        g_w2lT[(size_t)n * F1 + k] = l;
    }
}

// ----------------------------------------------------------------------------
// 0+1) init (zero counts + pooled) and int64/int32 detection, one launch
// ----------------------------------------------------------------------------
__global__ void init_detect_kernel(const int* __restrict__ ei) {
    int i = blockIdx.x * blockDim.x + threadIdx.x;
    if (i < N_NODES + 1) g_counts[i] = 0;
    if (i < OUT_C)       g_pooled[i] = 0.f;
    if (blockIdx.x == 0) {
        __shared__ int any;
        if (threadIdx.x == 0) any = 0;
        __syncthreads();
        for (int j = threadIdx.x; j < 4096; j += blockDim.x) {
            if (ei[2 * j + 1] != 0) any = 1;
        }
        __syncthreads();
        if (threadIdx.x == 0) g_is64 = (any == 0) ? 1 : 0;
    }
}

// ----------------------------------------------------------------------------
// 2) count in-degrees; 4 edges per thread (4x MLP on latency-bound atomics)
// ----------------------------------------------------------------------------
__global__ void count_kernel(const void* __restrict__ ei, int E) {
    int base = (blockIdx.x * blockDim.x + threadIdx.x) * 4;
    if (base >= E) return;
    int d[4];
    int n = (E - base < 4) ? (E - base) : 4;
    if (g_is64) {
        const long long* p = (const long long*)ei;
#pragma unroll
        for (int j = 0; j < 4; j++) if (j < n) d[j] = (int)p[E + base + j];
    } else {
        const int* p = (const int*)ei;
#pragma unroll
        for (int j = 0; j < 4; j++) if (j < n) d[j] = p[E + base + j];
    }
#pragma unroll
    for (int j = 0; j < 4; j++) if (j < n) atomicAdd(&g_counts[d[j]], 1);
}

// ----------------------------------------------------------------------------
// 3) parallel exclusive scan of g_counts -> g_rowptr / g_cursor  (PROVEN r4)
// ----------------------------------------------------------------------------
__global__ void __launch_bounds__(SCAN_BLOCK) scan1_kernel() {
    int i = blockIdx.x * SCAN_BLOCK + threadIdx.x;
    int v = (i < N_NODES) ? g_counts[i] : 0;
    __shared__ int sh[32];
    int lane = threadIdx.x & 31, w = threadIdx.x >> 5;
#pragma unroll
    for (int o = 16; o; o >>= 1) v += __shfl_xor_sync(~0u, v, o);
    if (lane == 0) sh[w] = v;
    __syncthreads();
    if (w == 0) {
        int s = sh[lane];
#pragma unroll
        for (int o = 16; o; o >>= 1) s += __shfl_xor_sync(~0u, s, o);
        if (lane == 0) g_blksum[blockIdx.x] = s;
    }
}

__global__ void scan2_kernel() {
    __shared__ int s[64];
    int t = threadIdx.x;
    int v = (t < SCAN_NBLK) ? g_blksum[t] : 0;
    s[t] = v;
    __syncthreads();
#pragma unroll
    for (int o = 1; o < 64; o <<= 1) {
        int u = (t >= o) ? s[t - o] : 0;
        __syncthreads();
        s[t] += u;
        __syncthreads();
    }
    if (t < SCAN_NBLK) g_blkoff[t] = s[t] - v;
    if (t == SCAN_NBLK - 1) g_rowptr[N_NODES] = s[t];
}

__global__ void __launch_bounds__(SCAN_BLOCK) scan3_kernel() {
    int b = blockIdx.x, t = threadIdx.x;
    int i = b * SCAN_BLOCK + t;
    int v = (i < N_NODES) ? g_counts[i] : 0;
    int lane = t & 31, w = t >> 5;
    int inc = v;
#pragma unroll
    for (int o = 1; o < 32; o <<= 1) {
        int u = __shfl_up_sync(~0u, inc, o);
        if (lane >= o) inc += u;
    }
    __shared__ int wsum[32];
    if (lane == 31) wsum[w] = inc;
    __syncthreads();
    if (w == 0) {
        int s = wsum[lane];
#pragma unroll
        for (int o = 1; o < 32; o <<= 1) {
            int u = __shfl_up_sync(~0u, s, o);
            if (lane >= o) s += u;
        }
        wsum[lane] = s;
    }
    __syncthreads();
    int exc = inc - v + (w > 0 ? wsum[w - 1] : 0) + g_blkoff[b];
    if (i < N_NODES) {
        g_rowptr[i] = exc;
        g_cursor[i] = exc;
    }
}

// ----------------------------------------------------------------------------
// 4) fill CSR directly from edge_index; 4 edges per thread (4x MLP)
// ----------------------------------------------------------------------------
__global__ void fill_kernel(const void* __restrict__ ei, int E) {
    int base = (blockIdx.x * blockDim.x + threadIdx.x) * 4;
    if (base >= E) return;
    int s[4], d[4];
    int n = (E - base < 4) ? (E - base) : 4;
    if (g_is64) {
        const long long* p = (const long long*)ei;
#pragma unroll
        for (int j = 0; j < 4; j++) if (j < n) { s[j] = (int)p[base + j]; d[j] = (int)p[E + base + j]; }
    } else {
        const int* p = (const int*)ei;
#pragma unroll
        for (int j = 0; j < 4; j++) if (j < n) { s[j] = p[base + j]; d[j] = p[E + base + j]; }
    }
    int pos[4];
#pragma unroll
    for (int j = 0; j < 4; j++) if (j < n) pos[j] = atomicAdd(&g_cursor[d[j]], 1);
#pragma unroll
    for (int j = 0; j < 4; j++) if (j < n) g_csr_src[pos[j]] = s[j];
}

// ----------------------------------------------------------------------------
// GEMM1 fused (2xFP16 HMMA, fp16 A / split B): h1 = x @ W1  (PROVEN r15)
// ----------------------------------------------------------------------------
__global__ void __launch_bounds__(256) gemm1_fused(const float* __restrict__ A,
                                                   const float* __restrict__ att_s,
                                                   const float* __restrict__ att_d) {
    constexpr int M = N_NODES, K = IN_C;
    constexpr int BM = 128, BN = 128, BK = 32;
    constexpr int SKA = BK + 8;
    __shared__ __half Ah[BM][SKA];
    __shared__ __half BhT[BN][SKA], BlT[BN][SKA];
    __shared__ float satt_s[BN], satt_d[BN];

    const int tid = threadIdx.x;
    const int lane = tid & 31, warp = tid >> 5;
    const int g = lane >> 2, t = lane & 3;
    const int warp_m = warp & 3;
    const int warp_n = warp >> 2;
    const int block_row = blockIdx.y * BM;
    const int block_col = blockIdx.x * BN;

    if (tid < BN) {
        satt_s[tid] = att_s[block_col + tid];
        satt_d[tid] = att_d[block_col + tid];
    }

    float acc[2][8][4];
#pragma unroll
    for (int mt = 0; mt < 2; mt++)
#pragma unroll
        for (int nt = 0; nt < 8; nt++)
#pragma unroll
            for (int q = 0; q < 4; q++) acc[mt][nt][q] = 0.f;

    for (int k0 = 0; k0 < K; k0 += BK) {
#pragma unroll
        for (int it = 0; it < 4; it++) {
            int idx = tid + it * 256;
            int r  = idx >> 3;
            int c4 = idx & 7;
            int gr = block_row + r;
            float4 v = make_float4(0.f, 0.f, 0.f, 0.f);
            if (gr < M) v = *(const float4*)(A + (size_t)gr * K + k0 + c4 * 4);
            int c = c4 * 4;
            Ah[r][c + 0] = __float2half(v.x);
            Ah[r][c + 1] = __float2half(v.y);
            Ah[r][c + 2] = __float2half(v.z);
            Ah[r][c + 3] = __float2half(v.w);
        }
#pragma unroll
        for (int it = 0; it < 2; it++) {
            int idx = tid + it * 256;
            int n = idx >> 2, c8 = idx & 3;
            *(uint4*)&BhT[n][c8 * 8] =
                *(const uint4*)&g_w1hT[(size_t)(block_col + n) * K + k0 + c8 * 8];
        }
#pragma unroll
        for (int it = 0; it < 2; it++) {
            int idx = tid + it * 256;
            int n = idx >> 2, c8 = idx & 3;
            *(uint4*)&BlT[n][c8 * 8] =
                *(const uint4*)&g_w1lT[(size_t)(block_col + n) * K + k0 + c8 * 8];
        }
        __syncthreads();
#pragma unroll
        for (int ks = 0; ks < 2; ks++) {
            const int kk = ks * 16;
            unsigned ah[2][4];
#pragma unroll
            for (int mt = 0; mt < 2; mt++) {
                int r0 = warp_m * 32 + mt * 16 + g;
                ah[mt][0] = *(const unsigned*)&Ah[r0][kk + 2 * t];
                ah[mt][1] = *(const unsigned*)&Ah[r0 + 8][kk + 2 * t];
                ah[mt][2] = *(const unsigned*)&Ah[r0][kk + 2 * t + 8];
                ah[mt][3] = *(const unsigned*)&Ah[r0 + 8][kk + 2 * t + 8];
            }
#pragma unroll
            for (int nt = 0; nt < 8; nt++) {
                int n0 = warp_n * 64 + nt * 8 + g;
                unsigned bh[2], bl[2];
                bh[0] = *(const unsigned*)&BhT[n0][kk + 2 * t];
                bh[1] = *(const unsigned*)&BhT[n0][kk + 2 * t + 8];
                bl[0] = *(const unsigned*)&BlT[n0][kk + 2 * t];
                bl[1] = *(const unsigned*)&BlT[n0][kk + 2 * t + 8];
#pragma unroll
                for (int mt = 0; mt < 2; mt++) {
                    mma_f16(acc[mt][nt], ah[mt], bl);   // small term first
                    mma_f16(acc[mt][nt], ah[mt], bh);
                }
            }
        }
        __syncthreads();
    }

    const int head = blockIdx.x * 2 + warp_n;
#pragma unroll
    for (int mt = 0; mt < 2; mt++) {
#pragma unroll
        for (int rr = 0; rr < 2; rr++) {
            int grow = block_row + warp_m * 32 + mt * 16 + g + rr * 8;
            bool valid = grow < M;
            float as_p = 0.f, ad_p = 0.f;
#pragma unroll
            for (int nt = 0; nt < 8; nt++) {
                float v0 = acc[mt][nt][rr * 2 + 0];
                float v1 = acc[mt][nt][rr * 2 + 1];
                int col = warp_n * 64 + nt * 8 + 2 * t;
                as_p += v0 * satt_s[col] + v1 * satt_s[col + 1];
                ad_p += v0 * satt_d[col] + v1 * satt_d[col + 1];
                if (valid) {
                    __nv_fp8x2_storage_t p = __nv_cvt_float2_to_fp8x2(
                        make_float2(v0, v1), __NV_SATFINITE, __NV_E4M3);
                    *(unsigned short*)&g_h1q[(size_t)grow * F1 + block_col + col] =
                        (unsigned short)p;
                }
            }
            as_p += __shfl_xor_sync(0xffffffffu, as_p, 1);
            as_p += __shfl_xor_sync(0xffffffffu, as_p, 2);
            ad_p += __shfl_xor_sync(0xffffffffu, ad_p, 1);
            ad_p += __shfl_xor_sync(0xffffffffu, ad_p, 2);
            if (t == 0 && valid) {
                g_as1[grow * HEADS + head] = as_p;
                g_ad1[grow * HEADS + head] = ad_p;
            }
        }
    }
}

// ----------------------------------------------------------------------------
// GEMM2 fused (2xFP16 HMMA, exact fp16 A): h2 = x2h @ W2
// Epilogue now stores fp8 h2 (values only; alpha logits stay fp32-exact).
// ----------------------------------------------------------------------------
__global__ void __launch_bounds__(128) gemm2_fused(const float* __restrict__ att_s,
                                                   const float* __restrict__ att_d) {
    constexpr int M = N_NODES, K = F1;
    constexpr int BM = 128, BN = 64, BK = 32;
    constexpr int SKA = BK + 8;
    const __half* A = g_x2h;
    __shared__ __half Ah[BM][SKA];
    __shared__ __half BhT[BN][SKA], BlT[BN][SKA];
    __shared__ float satt_s[BN], satt_d[BN];

    const int tid = threadIdx.x;
    const int lane = tid & 31, warp = tid >> 5;
    const int g = lane >> 2, t = lane & 3;
    const int block_row = blockIdx.y * BM;

    if (tid < BN) {
        satt_s[tid] = att_s[tid];
        satt_d[tid] = att_d[tid];
    }

    float acc[2][8][4];
#pragma unroll
    for (int mt = 0; mt < 2; mt++)
#pragma unroll
        for (int nt = 0; nt < 8; nt++)
#pragma unroll
            for (int q = 0; q < 4; q++) acc[mt][nt][q] = 0.f;

    for (int k0 = 0; k0 < K; k0 += BK) {
#pragma unroll
        for (int it = 0; it < 4; it++) {
            int idx = tid + it * 128;
            int r  = idx >> 2;
            int c8 = idx & 3;
            int gr = block_row + r;
            uint4 v = make_uint4(0u, 0u, 0u, 0u);
            if (gr < M) v = *(const uint4*)(A + (size_t)gr * K + k0 + c8 * 8);
            *(uint4*)&Ah[r][c8 * 8] = v;
        }
#pragma unroll
        for (int it = 0; it < 2; it++) {
            int idx = tid + it * 128;
            int n = idx >> 2, c8 = idx & 3;
            *(uint4*)&BhT[n][c8 * 8] =
                *(const uint4*)&g_w2hT[(size_t)n * K + k0 + c8 * 8];
        }
#pragma unroll
        for (int it = 0; it < 2; it++) {
            int idx = tid + it * 128;
            int n = idx >> 2, c8 = idx & 3;
            *(uint4*)&BlT[n][c8 * 8] =
                *(const uint4*)&g_w2lT[(size_t)n * K + k0 + c8 * 8];
        }
        __syncthreads();
#pragma unroll
        for (int ks = 0; ks < 2; ks++) {
            const int kk = ks * 16;
            unsigned ah[2][4];
#pragma unroll
            for (int mt = 0; mt < 2; mt++) {
                int r0 = warp * 32 + mt * 16 + g;
                ah[mt][0] = *(const unsigned*)&Ah[r0][kk + 2 * t];
                ah[mt][1] = *(const unsigned*)&Ah[r0 + 8][kk + 2 * t];
                ah[mt][2] = *(const unsigned*)&Ah[r0][kk + 2 * t + 8];
                ah[mt][3] = *(const unsigned*)&Ah[r0 + 8][kk + 2 * t + 8];
            }
#pragma unroll
            for (int nt = 0; nt < 8; nt++) {
                int n0 = nt * 8 + g;
                unsigned bh[2], bl[2];
                bh[0] = *(const unsigned*)&BhT[n0][kk + 2 * t];
                bh[1] = *(const unsigned*)&BhT[n0][kk + 2 * t + 8];
                bl[0] = *(const unsigned*)&BlT[n0][kk + 2 * t];
                bl[1] = *(const unsigned*)&BlT[n0][kk + 2 * t + 8];
#pragma unroll
                for (int mt = 0; mt < 2; mt++) {
                    mma_f16(acc[mt][nt], ah[mt], bl);
                    mma_f16(acc[mt][nt], ah[mt], bh);
                }
            }
        }
        __syncthreads();
    }

#pragma unroll
    for (int mt = 0; mt < 2; mt++) {
#pragma unroll
        for (int rr = 0; rr < 2; rr++) {
            int grow = block_row + warp * 32 + mt * 16 + g + rr * 8;
            bool valid = grow < M;
            float as_p = 0.f, ad_p = 0.f;
#pragma unroll
            for (int nt = 0; nt < 8; nt++) {
                float v0 = acc[mt][nt][rr * 2 + 0];
                float v1 = acc[mt][nt][rr * 2 + 1];
                int col = nt * 8 + 2 * t;
                as_p += v0 * satt_s[col] + v1 * satt_s[col + 1];
                ad_p += v0 * satt_d[col] + v1 * satt_d[col + 1];
                if (valid) {
                    __nv_fp8x2_storage_t p = __nv_cvt_float2_to_fp8x2(
                        make_float2(v0, v1), __NV_SATFINITE, __NV_E4M3);
                    *(unsigned short*)&g_h2q[(size_t)grow * OUT_C + col] =
                        (unsigned short)p;
                }
            }
            as_p += __shfl_xor_sync(0xffffffffu, as_p, 1);
            as_p += __shfl_xor_sync(0xffffffffu, as_p, 2);
            ad_p += __shfl_xor_sync(0xffffffffu, ad_p, 1);
            ad_p += __shfl_xor_sync(0xffffffffu, ad_p, 2);
            if (t == 0 && valid) {
                g_as2[grow] = as_p;
                g_ad2[grow] = ad_p;
            }
        }
    }
}

// ----------------------------------------------------------------------------
// Layer-1 aggregation (PROVEN r10/r15): warp per dst node, single-pass
// softmax, FP8 gathers, fp32 accumulation, fp16 x2 output.
// ----------------------------------------------------------------------------
__global__ void agg1_kernel(const float* __restrict__ b1) {
    int t = threadIdx.x;
    int warp = (blockIdx.x * blockDim.x + t) >> 5;
    if (warp >= N_NODES) return;
    int lane = t & 31;
    int d = warp;
    int head = lane >> 3;

    float ad = g_ad1[d * HEADS + head];
    int beg = g_rowptr[d], end = g_rowptr[d + 1];

    float denom = 1e-16f;
    float acc[8] = {0.f, 0.f, 0.f, 0.f, 0.f, 0.f, 0.f, 0.f};
    for (int i = beg; i < end; i++) {
        int s = g_csr_src[i];
        float w = __expf(lrelu(g_as1[s * HEADS + head] + ad));
        denom += w;
        uint2 u = *(const uint2*)&g_h1q[(size_t)s * F1 + lane * 8];
        float2 f0 = fp8x2_to_float2((unsigned short)(u.x & 0xffffu));
        float2 f1 = fp8x2_to_float2((unsigned short)(u.x >> 16));
        float2 f2 = fp8x2_to_float2((unsigned short)(u.y & 0xffffu));
        float2 f3 = fp8x2_to_float2((unsigned short)(u.y >> 16));
        acc[0] += w * f0.x; acc[1] += w * f0.y;
        acc[2] += w * f1.x; acc[3] += w * f1.y;
        acc[4] += w * f2.x; acc[5] += w * f2.y;
        acc[6] += w * f3.x; acc[7] += w * f3.y;
    }
    {   // self loop
        float w = __expf(lrelu(g_as1[d * HEADS + head] + ad));
        denom += w;
        uint2 u = *(const uint2*)&g_h1q[(size_t)d * F1 + lane * 8];
        float2 f0 = fp8x2_to_float2((unsigned short)(u.x & 0xffffu));
        float2 f1 = fp8x2_to_float2((unsigned short)(u.x >> 16));
        float2 f2 = fp8x2_to_float2((unsigned short)(u.y & 0xffffu));
        float2 f3 = fp8x2_to_float2((unsigned short)(u.y >> 16));
        acc[0] += w * f0.x; acc[1] += w * f0.y;
        acc[2] += w * f1.x; acc[3] += w * f1.y;
        acc[4] += w * f2.x; acc[5] += w * f2.y;
        acc[6] += w * f3.x; acc[7] += w * f3.y;
    }
    float inv = 1.f / denom;
    int cb = lane * 8;
    __half hbuf[8];
#pragma unroll
    for (int j = 0; j < 8; j++)
        hbuf[j] = __float2half(fmaxf(acc[j] * inv + b1[cb + j], 0.f));
    *(uint4*)&g_x2h[(size_t)d * F1 + cb] = *(uint4*)hbuf;
}

// ----------------------------------------------------------------------------
// Layer-2 aggregation + pool: fp8 gathers (lane covers cols 2*lane, 2*lane+1).
// Same loop structure as proven r10; only the feature dtype/indexing changed.
// ----------------------------------------------------------------------------
__global__ void agg2_pool_kernel(const float* __restrict__ b2) {
    __shared__ float sp[OUT_C];
    int t = threadIdx.x;
    if (t < OUT_C) sp[t] = 0.f;
    __syncthreads();

    int warp = (blockIdx.x * blockDim.x + t) >> 5;
    int lane = t & 31;
    if (warp < N_NODES) {
        int d = warp;
        float ad = g_ad2[d];
        int beg = g_rowptr[d], end = g_rowptr[d + 1];

        float denom = 1e-16f;
        float a0 = 0.f, a1 = 0.f;
        for (int i = beg; i < end; i++) {
            int s = g_csr_src[i];
            float w = __expf(lrelu(g_as2[s] + ad));
            denom += w;
            unsigned short u = *(const unsigned short*)&g_h2q[(size_t)s * OUT_C + lane * 2];
            float2 f = fp8x2_to_float2(u);
            a0 += w * f.x;
            a1 += w * f.y;
        }
        {
            float w = __expf(lrelu(g_as2[d] + ad));
            denom += w;
            unsigned short u = *(const unsigned short*)&g_h2q[(size_t)d * OUT_C + lane * 2];
            float2 f = fp8x2_to_float2(u);
            a0 += w * f.x;
            a1 += w * f.y;
        }
        float inv = 1.f / denom;
        float v0 = fmaxf(a0 * inv + b2[lane * 2 + 0], 0.f);
        float v1 = fmaxf(a1 * inv + b2[lane * 2 + 1], 0.f);
        atomicAdd(&sp[lane * 2 + 0], v0);
        atomicAdd(&sp[lane * 2 + 1], v1);
    }
    __syncthreads();
    if (t < OUT_C) atomicAdd(&g_pooled[t], sp[t]);
}

// ----------------------------------------------------------------------------
// Final: mean-pool scale, FC to 40 classes, log_softmax
// ----------------------------------------------------------------------------
__global__ void final_kernel(const float* __restrict__ fc_w,
                             const float* __restrict__ fc_b,
                             float* __restrict__ out) {
    __shared__ float p[OUT_C];
    __shared__ float lg[NUM_CLASSES];
    __shared__ float lse_sh;
    int t = threadIdx.x;  // 64 threads
    p[t] = g_pooled[t] * (1.0f / (float)N_NODES);
    __syncthreads();
    if (t < NUM_CLASSES) {
        float s = fc_b[t];
#pragma unroll
        for (int c = 0; c < OUT_C; c++) s += p[c] * fc_w[c * NUM_CLASSES + t];
        lg[t] = s;
    }
    __syncthreads();
    if (t == 0) {
        float mx = lg[0];
        for (int j = 1; j < NUM_CLASSES; j++) mx = fmaxf(mx, lg[j]);
        float se = 0.f;
        for (int j = 0; j < NUM_CLASSES; j++) se += expf(lg[j] - mx);
        lse_sh = mx + logf(se);
    }
    __syncthreads();
    if (t < NUM_CLASSES) out[t] = lg[t] - lse_sh;
}

// ----------------------------------------------------------------------------
// launch: CSR build (side stream) overlaps wsplit+gemm1 (main stream).
// ----------------------------------------------------------------------------
extern "C" void kernel_launch(void* const* d_in, const int* in_sizes, int n_in,
                              void* d_out, int out_size) {
    const float* x      = (const float*)d_in[0];
    const void*  ei     = d_in[1];
    const float* W1     = (const float*)d_in[2];
    const float* att_s1 = (const float*)d_in[3];
    const float* att_d1 = (const float*)d_in[4];
    const float* b1     = (const float*)d_in[5];
    const float* W2     = (const float*)d_in[6];
    const float* att_s2 = (const float*)d_in[7];
    const float* att_d2 = (const float*)d_in[8];
    const float* b2     = (const float*)d_in[9];
    const float* fc_w   = (const float*)d_in[10];
    const float* fc_b   = (const float*)d_in[11];
    float* out = (float*)d_out;

    int E = in_sizes[1] / 2;
    if (E > E_MAX) E = E_MAX;

    const int WARPS_PER_BLOCK = 8;
    const int nodeBlocks = (N_NODES + WARPS_PER_BLOCK - 1) / WARPS_PER_BLOCK;
    const int mBlocks = (N_NODES + 127) / 128;
    const int edge4Blocks = ((E + 3) / 4 + 255) / 256;

    static cudaStream_t s_side = nullptr;
    static cudaEvent_t  ev_fork = nullptr, ev_join = nullptr;
    if (s_side == nullptr) {
        cudaStreamCreateWithFlags(&s_side, cudaStreamNonBlocking);
        cudaEventCreateWithFlags(&ev_fork, cudaEventDisableTiming);
        cudaEventCreateWithFlags(&ev_join, cudaEventDisableTiming);
    }

    // Fork: CSR-build chain on side stream
    cudaEventRecord(ev_fork, 0);
    cudaStreamWaitEvent(s_side, ev_fork, 0);

    init_detect_kernel<<<(N_NODES + 256) / 256, 256, 0, s_side>>>((const int*)ei);
    count_kernel<<<edge4Blocks, 256, 0, s_side>>>(ei, E);
    scan1_kernel<<<SCAN_NBLK, SCAN_BLOCK, 0, s_side>>>();
    scan2_kernel<<<1, 64, 0, s_side>>>();
    scan3_kernel<<<SCAN_NBLK, SCAN_BLOCK, 0, s_side>>>();
    fill_kernel<<<edge4Blocks, 256, 0, s_side>>>(ei, E);
    cudaEventRecord(ev_join, s_side);

    // Concurrent on main stream: weight split + layer-1 GEMM
    wsplit_kernel<<<(IN_C * F1 + 255) / 256, 256>>>(W1, W2);
    gemm1_fused<<<dim3(F1 / 128, mBlocks), 256>>>(x, att_s1, att_d1);

    // Join: agg1 needs both CSR and gemm1
    cudaStreamWaitEvent(0, ev_join, 0);

    agg1_kernel<<<nodeBlocks, 256>>>(b1);
    gemm2_fused<<<dim3(1, mBlocks), 128>>>(att_s2, att_d2);
    agg2_pool_kernel<<<nodeBlocks, 256>>>(b2);
    final_kernel<<<1, 64>>>(fc_w, fc_b, out);
}

// round 17
// speedup vs baseline: 1.1613x; 1.0435x over previous
#include <cuda_runtime.h>
#include <cuda_bf16.h>
#include <cuda_fp16.h>
#include <cuda_fp8.h>
#include <math.h>

// Problem constants (fixed by the reference)
#define N_NODES 50000
#define E_MAX   800000
#define IN_C    128
#define HID     64
#define HEADS   4
#define F1      (HEADS*HID)   // 256
#define OUT_C   64
#define NUM_CLASSES 40

#define SCAN_BLOCK 1024
#define SCAN_NBLK  ((N_NODES + SCAN_BLOCK - 1) / SCAN_BLOCK)   // 49

// ----------------------------------------------------------------------------
// Scratch (device globals: allocation-free per harness rules)
// ----------------------------------------------------------------------------
__device__ unsigned char g_h1q[(size_t)N_NODES * F1];   // layer-1 features, fp8 e4m3
__device__ __half g_x2h[(size_t)N_NODES * F1];          // layer-1 GAT output, fp16
__device__ unsigned char g_h2q[(size_t)N_NODES * OUT_C];// layer-2 features, fp8 e4m3
__device__ __half g_w1hT[(size_t)F1 * IN_C];            // W1^T hi  [n][k]
__device__ __half g_w1lT[(size_t)F1 * IN_C];            // W1^T lo
__device__ __half g_w2hT[(size_t)OUT_C * F1];           // W2^T hi
__device__ __half g_w2lT[(size_t)OUT_C * F1];           // W2^T lo
__device__ float  g_as1[N_NODES * HEADS];
__device__ float  g_ad1[N_NODES * HEADS];
__device__ float  g_as2[N_NODES];
__device__ float  g_ad2[N_NODES];
__device__ int    g_counts[N_NODES + 1];
__device__ int    g_rowptr[N_NODES + 1];
__device__ int    g_cursor[N_NODES];
__device__ int    g_csr_src[E_MAX];
__device__ int    g_blksum[SCAN_NBLK];
__device__ int    g_blkoff[SCAN_NBLK];
__device__ float  g_pooled[OUT_C];
__device__ int    g_is64;

__device__ __forceinline__ float lrelu(float v) { return v > 0.f ? v : 0.2f * v; }

__device__ __forceinline__ void split_h(float v, __half& hi, __half& lo) {
    hi = __float2half(v);
    lo = __float2half(v - __half2float(hi));
}

__device__ __forceinline__ __half2 fp8x2_to_half2(unsigned short v) {
    __half2_raw hr = __nv_cvt_fp8x2_to_halfraw2((__nv_fp8x2_storage_t)v, __NV_E4M3);
    return *reinterpret_cast<__half2*>(&hr);
}

// m16n8k16 fp16 MMA, fp32 accumulate
__device__ __forceinline__ void mma_f16(float* c, const unsigned* a, const unsigned* b) {
    asm volatile(
        "mma.sync.aligned.m16n8k16.row.col.f32.f16.f16.f32 "
        "{%0,%1,%2,%3}, {%4,%5,%6,%7}, {%8,%9}, {%0,%1,%2,%3};\n"
        : "+f"(c[0]), "+f"(c[1]), "+f"(c[2]), "+f"(c[3])
        : "r"(a[0]), "r"(a[1]), "r"(a[2]), "r"(a[3]), "r"(b[0]), "r"(b[1]));
}

// ----------------------------------------------------------------------------
// W pre-split + transpose: W1[k][n] -> w1{h,l}T[n][k]; W2 likewise. Tiny.
// ----------------------------------------------------------------------------
__global__ void wsplit_kernel(const float* __restrict__ W1,
                              const float* __restrict__ W2) {
    int i = blockIdx.x * blockDim.x + threadIdx.x;
    if (i < IN_C * F1) {
        int k = i / F1, n = i % F1;
        __half h, l; split_h(W1[i], h, l);
        g_w1hT[(size_t)n * IN_C + k] = h;
        g_w1lT[(size_t)n * IN_C + k] = l;
    }
    if (i < F1 * OUT_C) {
        int k = i / OUT_C, n = i % OUT_C;
        __half h, l; split_h(W2[i], h, l);
        g_w2hT[(size_t)n * F1 + k] = h;
        g_w2lT[(size_t)n * F1 + k] = l;
    }
}

// ----------------------------------------------------------------------------
// 0+1) init (zero counts + pooled) and int64/int32 detection, one launch
// ----------------------------------------------------------------------------
__global__ void init_detect_kernel(const int* __restrict__ ei) {
    int i = blockIdx.x * blockDim.x + threadIdx.x;
    if (i < N_NODES + 1) g_counts[i] = 0;
    if (i < OUT_C)       g_pooled[i] = 0.f;
    if (blockIdx.x == 0) {
        __shared__ int any;
        if (threadIdx.x == 0) any = 0;
        __syncthreads();
        for (int j = threadIdx.x; j < 4096; j += blockDim.x) {
            if (ei[2 * j + 1] != 0) any = 1;
        }
        __syncthreads();
        if (threadIdx.x == 0) g_is64 = (any == 0) ? 1 : 0;
    }
}

// ----------------------------------------------------------------------------
// 2) count in-degrees; 4 edges per thread
// ----------------------------------------------------------------------------
__global__ void count_kernel(const void* __restrict__ ei, int E) {
    int base = (blockIdx.x * blockDim.x + threadIdx.x) * 4;
    if (base >= E) return;
    int d[4];
    int n = (E - base < 4) ? (E - base) : 4;
    if (g_is64) {
        const long long* p = (const long long*)ei;
#pragma unroll
        for (int j = 0; j < 4; j++) if (j < n) d[j] = (int)p[E + base + j];
    } else {
        const int* p = (const int*)ei;
#pragma unroll
        for (int j = 0; j < 4; j++) if (j < n) d[j] = p[E + base + j];
    }
#pragma unroll
    for (int j = 0; j < 4; j++) if (j < n) atomicAdd(&g_counts[d[j]], 1);
}

// ----------------------------------------------------------------------------
// 3) parallel exclusive scan of g_counts -> g_rowptr / g_cursor  (PROVEN r4)
// ----------------------------------------------------------------------------
__global__ void __launch_bounds__(SCAN_BLOCK) scan1_kernel() {
    int i = blockIdx.x * SCAN_BLOCK + threadIdx.x;
    int v = (i < N_NODES) ? g_counts[i] : 0;
    __shared__ int sh[32];
    int lane = threadIdx.x & 31, w = threadIdx.x >> 5;
#pragma unroll
    for (int o = 16; o; o >>= 1) v += __shfl_xor_sync(~0u, v, o);
    if (lane == 0) sh[w] = v;
    __syncthreads();
    if (w == 0) {
        int s = sh[lane];
#pragma unroll
        for (int o = 16; o; o >>= 1) s += __shfl_xor_sync(~0u, s, o);
        if (lane == 0) g_blksum[blockIdx.x] = s;
    }
}

__global__ void scan2_kernel() {
    __shared__ int s[64];
    int t = threadIdx.x;
    int v = (t < SCAN_NBLK) ? g_blksum[t] : 0;
    s[t] = v;
    __syncthreads();
#pragma unroll
    for (int o = 1; o < 64; o <<= 1) {
        int u = (t >= o) ? s[t - o] : 0;
        __syncthreads();
        s[t] += u;
        __syncthreads();
    }
    if (t < SCAN_NBLK) g_blkoff[t] = s[t] - v;
    if (t == SCAN_NBLK - 1) g_rowptr[N_NODES] = s[t];
}

__global__ void __launch_bounds__(SCAN_BLOCK) scan3_kernel() {
    int b = blockIdx.x, t = threadIdx.x;
    int i = b * SCAN_BLOCK + t;
    int v = (i < N_NODES) ? g_counts[i] : 0;
    int lane = t & 31, w = t >> 5;
    int inc = v;
#pragma unroll
    for (int o = 1; o < 32; o <<= 1) {
        int u = __shfl_up_sync(~0u, inc, o);
        if (lane >= o) inc += u;
    }
    __shared__ int wsum[32];
    if (lane == 31) wsum[w] = inc;
    __syncthreads();
    if (w == 0) {
        int s = wsum[lane];
#pragma unroll
        for (int o = 1; o < 32; o <<= 1) {
            int u = __shfl_up_sync(~0u, s, o);
            if (lane >= o) s += u;
        }
        wsum[lane] = s;
    }
    __syncthreads();
    int exc = inc - v + (w > 0 ? wsum[w - 1] : 0) + g_blkoff[b];
    if (i < N_NODES) {
        g_rowptr[i] = exc;
        g_cursor[i] = exc;
    }
}

// ----------------------------------------------------------------------------
// 4) fill CSR directly from edge_index; 4 edges per thread
// ----------------------------------------------------------------------------
__global__ void fill_kernel(const void* __restrict__ ei, int E) {
    int base = (blockIdx.x * blockDim.x + threadIdx.x) * 4;
    if (base >= E) return;
    int s[4], d[4];
    int n = (E - base < 4) ? (E - base) : 4;
    if (g_is64) {
        const long long* p = (const long long*)ei;
#pragma unroll
        for (int j = 0; j < 4; j++) if (j < n) { s[j] = (int)p[base + j]; d[j] = (int)p[E + base + j]; }
    } else {
        const int* p = (const int*)ei;
#pragma unroll
        for (int j = 0; j < 4; j++) if (j < n) { s[j] = p[base + j]; d[j] = p[E + base + j]; }
    }
    int pos[4];
#pragma unroll
    for (int j = 0; j < 4; j++) if (j < n) pos[j] = atomicAdd(&g_cursor[d[j]], 1);
#pragma unroll
    for (int j = 0; j < 4; j++) if (j < n) g_csr_src[pos[j]] = s[j];
}

// ----------------------------------------------------------------------------
// GEMM1 fused (2xFP16 HMMA, fp16 A / split B): h1 = x @ W1  (PROVEN r15)
// ----------------------------------------------------------------------------
__global__ void __launch_bounds__(256) gemm1_fused(const float* __restrict__ A,
                                                   const float* __restrict__ att_s,
                                                   const float* __restrict__ att_d) {
    constexpr int M = N_NODES, K = IN_C;
    constexpr int BM = 128, BN = 128, BK = 32;
    constexpr int SKA = BK + 8;
    __shared__ __half Ah[BM][SKA];
    __shared__ __half BhT[BN][SKA], BlT[BN][SKA];
    __shared__ float satt_s[BN], satt_d[BN];

    const int tid = threadIdx.x;
    const int lane = tid & 31, warp = tid >> 5;
    const int g = lane >> 2, t = lane & 3;
    const int warp_m = warp & 3;
    const int warp_n = warp >> 2;
    const int block_row = blockIdx.y * BM;
    const int block_col = blockIdx.x * BN;

    if (tid < BN) {
        satt_s[tid] = att_s[block_col + tid];
        satt_d[tid] = att_d[block_col + tid];
    }

    float acc[2][8][4];
#pragma unroll
    for (int mt = 0; mt < 2; mt++)
#pragma unroll
        for (int nt = 0; nt < 8; nt++)
#pragma unroll
            for (int q = 0; q < 4; q++) acc[mt][nt][q] = 0.f;

    for (int k0 = 0; k0 < K; k0 += BK) {
#pragma unroll
        for (int it = 0; it < 4; it++) {
            int idx = tid + it * 256;
            int r  = idx >> 3;
            int c4 = idx & 7;
            int gr = block_row + r;
            float4 v = make_float4(0.f, 0.f, 0.f, 0.f);
            if (gr < M) v = *(const float4*)(A + (size_t)gr * K + k0 + c4 * 4);
            int c = c4 * 4;
            Ah[r][c + 0] = __float2half(v.x);
            Ah[r][c + 1] = __float2half(v.y);
            Ah[r][c + 2] = __float2half(v.z);
            Ah[r][c + 3] = __float2half(v.w);
        }
#pragma unroll
        for (int it = 0; it < 2; it++) {
            int idx = tid + it * 256;
            int n = idx >> 2, c8 = idx & 3;
            *(uint4*)&BhT[n][c8 * 8] =
                *(const uint4*)&g_w1hT[(size_t)(block_col + n) * K + k0 + c8 * 8];
        }
#pragma unroll
        for (int it = 0; it < 2; it++) {
            int idx = tid + it * 256;
            int n = idx >> 2, c8 = idx & 3;
            *(uint4*)&BlT[n][c8 * 8] =
                *(const uint4*)&g_w1lT[(size_t)(block_col + n) * K + k0 + c8 * 8];
        }
        __syncthreads();
#pragma unroll
        for (int ks = 0; ks < 2; ks++) {
            const int kk = ks * 16;
            unsigned ah[2][4];
#pragma unroll
            for (int mt = 0; mt < 2; mt++) {
                int r0 = warp_m * 32 + mt * 16 + g;
                ah[mt][0] = *(const unsigned*)&Ah[r0][kk + 2 * t];
                ah[mt][1] = *(const unsigned*)&Ah[r0 + 8][kk + 2 * t];
                ah[mt][2] = *(const unsigned*)&Ah[r0][kk + 2 * t + 8];
                ah[mt][3] = *(const unsigned*)&Ah[r0 + 8][kk + 2 * t + 8];
            }
#pragma unroll
            for (int nt = 0; nt < 8; nt++) {
                int n0 = warp_n * 64 + nt * 8 + g;
                unsigned bh[2], bl[2];
                bh[0] = *(const unsigned*)&BhT[n0][kk + 2 * t];
                bh[1] = *(const unsigned*)&BhT[n0][kk + 2 * t + 8];
                bl[0] = *(const unsigned*)&BlT[n0][kk + 2 * t];
                bl[1] = *(const unsigned*)&BlT[n0][kk + 2 * t + 8];
#pragma unroll
                for (int mt = 0; mt < 2; mt++) {
                    mma_f16(acc[mt][nt], ah[mt], bl);   // small term first
                    mma_f16(acc[mt][nt], ah[mt], bh);
                }
            }
        }
        __syncthreads();
    }

    const int head = blockIdx.x * 2 + warp_n;
#pragma unroll
    for (int mt = 0; mt < 2; mt++) {
#pragma unroll
        for (int rr = 0; rr < 2; rr++) {
            int grow = block_row + warp_m * 32 + mt * 16 + g + rr * 8;
            bool valid = grow < M;
            float as_p = 0.f, ad_p = 0.f;
#pragma unroll
            for (int nt = 0; nt < 8; nt++) {
                float v0 = acc[mt][nt][rr * 2 + 0];
                float v1 = acc[mt][nt][rr * 2 + 1];
                int col = warp_n * 64 + nt * 8 + 2 * t;
                as_p += v0 * satt_s[col] + v1 * satt_s[col + 1];
                ad_p += v0 * satt_d[col] + v1 * satt_d[col + 1];
                if (valid) {
                    __nv_fp8x2_storage_t p = __nv_cvt_float2_to_fp8x2(
                        make_float2(v0, v1), __NV_SATFINITE, __NV_E4M3);
                    *(unsigned short*)&g_h1q[(size_t)grow * F1 + block_col + col] =
                        (unsigned short)p;
                }
            }
            as_p += __shfl_xor_sync(0xffffffffu, as_p, 1);
            as_p += __shfl_xor_sync(0xffffffffu, as_p, 2);
            ad_p += __shfl_xor_sync(0xffffffffu, ad_p, 1);
            ad_p += __shfl_xor_sync(0xffffffffu, ad_p, 2);
            if (t == 0 && valid) {
                g_as1[grow * HEADS + head] = as_p;
                g_ad1[grow * HEADS + head] = ad_p;
            }
        }
    }
}

// ----------------------------------------------------------------------------
// GEMM2 fused (2xFP16 HMMA, exact fp16 A): h2 = x2h @ W2  (PROVEN r16)
// ----------------------------------------------------------------------------
__global__ void __launch_bounds__(128) gemm2_fused(const float* __restrict__ att_s,
                                                   const float* __restrict__ att_d) {
    constexpr int M = N_NODES, K = F1;
    constexpr int BM = 128, BN = 64, BK = 32;
    constexpr int SKA = BK + 8;
    const __half* A = g_x2h;
    __shared__ __half Ah[BM][SKA];
    __shared__ __half BhT[BN][SKA], BlT[BN][SKA];
    __shared__ float satt_s[BN], satt_d[BN];

    const int tid = threadIdx.x;
    const int lane = tid & 31, warp = tid >> 5;
    const int g = lane >> 2, t = lane & 3;
    const int block_row = blockIdx.y * BM;

    if (tid < BN) {
        satt_s[tid] = att_s[tid];
        satt_d[tid] = att_d[tid];
    }

    float acc[2][8][4];
#pragma unroll
    for (int mt = 0; mt < 2; mt++)
#pragma unroll
        for (int nt = 0; nt < 8; nt++)
#pragma unroll
            for (int q = 0; q < 4; q++) acc[mt][nt][q] = 0.f;

    for (int k0 = 0; k0 < K; k0 += BK) {
#pragma unroll
        for (int it = 0; it < 4; it++) {
            int idx = tid + it * 128;
            int r  = idx >> 2;
            int c8 = idx & 3;
            int gr = block_row + r;
            uint4 v = make_uint4(0u, 0u, 0u, 0u);
            if (gr < M) v = *(const uint4*)(A + (size_t)gr * K + k0 + c8 * 8);
            *(uint4*)&Ah[r][c8 * 8] = v;
        }
#pragma unroll
        for (int it = 0; it < 2; it++) {
            int idx = tid + it * 128;
            int n = idx >> 2, c8 = idx & 3;
            *(uint4*)&BhT[n][c8 * 8] =
                *(const uint4*)&g_w2hT[(size_t)n * K + k0 + c8 * 8];
        }
#pragma unroll
        for (int it = 0; it < 2; it++) {
            int idx = tid + it * 128;
            int n = idx >> 2, c8 = idx & 3;
            *(uint4*)&BlT[n][c8 * 8] =
                *(const uint4*)&g_w2lT[(size_t)n * K + k0 + c8 * 8];
        }
        __syncthreads();
#pragma unroll
        for (int ks = 0; ks < 2; ks++) {
            const int kk = ks * 16;
            unsigned ah[2][4];
#pragma unroll
            for (int mt = 0; mt < 2; mt++) {
                int r0 = warp * 32 + mt * 16 + g;
                ah[mt][0] = *(const unsigned*)&Ah[r0][kk + 2 * t];
                ah[mt][1] = *(const unsigned*)&Ah[r0 + 8][kk + 2 * t];
                ah[mt][2] = *(const unsigned*)&Ah[r0][kk + 2 * t + 8];
                ah[mt][3] = *(const unsigned*)&Ah[r0 + 8][kk + 2 * t + 8];
            }
#pragma unroll
            for (int nt = 0; nt < 8; nt++) {
                int n0 = nt * 8 + g;
                unsigned bh[2], bl[2];
                bh[0] = *(const unsigned*)&BhT[n0][kk + 2 * t];
                bh[1] = *(const unsigned*)&BhT[n0][kk + 2 * t + 8];
                bl[0] = *(const unsigned*)&BlT[n0][kk + 2 * t];
                bl[1] = *(const unsigned*)&BlT[n0][kk + 2 * t + 8];
#pragma unroll
                for (int mt = 0; mt < 2; mt++) {
                    mma_f16(acc[mt][nt], ah[mt], bl);
                    mma_f16(acc[mt][nt], ah[mt], bh);
                }
            }
        }
        __syncthreads();
    }

#pragma unroll
    for (int mt = 0; mt < 2; mt++) {
#pragma unroll
        for (int rr = 0; rr < 2; rr++) {
            int grow = block_row + warp * 32 + mt * 16 + g + rr * 8;
            bool valid = grow < M;
            float as_p = 0.f, ad_p = 0.f;
#pragma unroll
            for (int nt = 0; nt < 8; nt++) {
                float v0 = acc[mt][nt][rr * 2 + 0];
                float v1 = acc[mt][nt][rr * 2 + 1];
                int col = nt * 8 + 2 * t;
                as_p += v0 * satt_s[col] + v1 * satt_s[col + 1];
                ad_p += v0 * satt_d[col] + v1 * satt_d[col + 1];
                if (valid) {
                    __nv_fp8x2_storage_t p = __nv_cvt_float2_to_fp8x2(
                        make_float2(v0, v1), __NV_SATFINITE, __NV_E4M3);
                    *(unsigned short*)&g_h2q[(size_t)grow * OUT_C + col] =
                        (unsigned short)p;
                }
            }
            as_p += __shfl_xor_sync(0xffffffffu, as_p, 1);
            as_p += __shfl_xor_sync(0xffffffffu, as_p, 2);
            ad_p += __shfl_xor_sync(0xffffffffu, ad_p, 1);
            ad_p += __shfl_xor_sync(0xffffffffu, ad_p, 2);
            if (t == 0 && valid) {
                g_as2[grow] = as_p;
                g_ad2[grow] = ad_p;
            }
        }
    }
}

// ----------------------------------------------------------------------------
// Layer-1 aggregation: warp per dst node, single-pass softmax, FP8 gathers,
// HALF2 accumulation (4 HFMA2/edge; fp32 logits/denom; fp32 epilogue).
// ----------------------------------------------------------------------------
__global__ void agg1_kernel(const float* __restrict__ b1) {
    int t = threadIdx.x;
    int warp = (blockIdx.x * blockDim.x + t) >> 5;
    if (warp >= N_NODES) return;
    int lane = t & 31;
    int d = warp;
    int head = lane >> 3;

    float ad = g_ad1[d * HEADS + head];
    int beg = g_rowptr[d], end = g_rowptr[d + 1];

    float denom = 1e-16f;
    __half2 acc0 = __float2half2_rn(0.f);
    __half2 acc1 = __float2half2_rn(0.f);
    __half2 acc2 = __float2half2_rn(0.f);
    __half2 acc3 = __float2half2_rn(0.f);

    for (int i = beg; i < end; i++) {
        int s = g_csr_src[i];
        float w = __expf(lrelu(g_as1[s * HEADS + head] + ad));
        denom += w;
        __half2 wh = __float2half2_rn(w);
        uint2 u = *(const uint2*)&g_h1q[(size_t)s * F1 + lane * 8];
        acc0 = __hfma2(fp8x2_to_half2((unsigned short)(u.x & 0xffffu)), wh, acc0);
        acc1 = __hfma2(fp8x2_to_half2((unsigned short)(u.x >> 16)),    wh, acc1);
        acc2 = __hfma2(fp8x2_to_half2((unsigned short)(u.y & 0xffffu)), wh, acc2);
        acc3 = __hfma2(fp8x2_to_half2((unsigned short)(u.y >> 16)),    wh, acc3);
    }
    {   // self loop
        float w = __expf(lrelu(g_as1[d * HEADS + head] + ad));
        denom += w;
        __half2 wh = __float2half2_rn(w);
        uint2 u = *(const uint2*)&g_h1q[(size_t)d * F1 + lane * 8];
        acc0 = __hfma2(fp8x2_to_half2((unsigned short)(u.x & 0xffffu)), wh, acc0);
        acc1 = __hfma2(fp8x2_to_half2((unsigned short)(u.x >> 16)),    wh, acc1);
        acc2 = __hfma2(fp8x2_to_half2((unsigned short)(u.y & 0xffffu)), wh, acc2);
        acc3 = __hfma2(fp8x2_to_half2((unsigned short)(u.y >> 16)),    wh, acc3);
    }
    float inv = 1.f / denom;
    float2 f0 = __half22float2(acc0);
    float2 f1 = __half22float2(acc1);
    float2 f2 = __half22float2(acc2);
    float2 f3 = __half22float2(acc3);
    int cb = lane * 8;
    __half hbuf[8];
    hbuf[0] = __float2half(fmaxf(f0.x * inv + b1[cb + 0], 0.f));
    hbuf[1] = __float2half(fmaxf(f0.y * inv + b1[cb + 1], 0.f));
    hbuf[2] = __float2half(fmaxf(f1.x * inv + b1[cb + 2], 0.f));
    hbuf[3] = __float2half(fmaxf(f1.y * inv + b1[cb + 3], 0.f));
    hbuf[4] = __float2half(fmaxf(f2.x * inv + b1[cb + 4], 0.f));
    hbuf[5] = __float2half(fmaxf(f2.y * inv + b1[cb + 5], 0.f));
    hbuf[6] = __float2half(fmaxf(f3.x * inv + b1[cb + 6], 0.f));
    hbuf[7] = __float2half(fmaxf(f3.y * inv + b1[cb + 7], 0.f));
    *(uint4*)&g_x2h[(size_t)d * F1 + cb] = *(uint4*)hbuf;
}

// ----------------------------------------------------------------------------
// Layer-2 aggregation + pool: fp8 gathers, HALF2 accumulation (1 HFMA2/edge).
// ----------------------------------------------------------------------------
__global__ void agg2_pool_kernel(const float* __restrict__ b2) {
    __shared__ float sp[OUT_C];
    int t = threadIdx.x;
    if (t < OUT_C) sp[t] = 0.f;
    __syncthreads();

    int warp = (blockIdx.x * blockDim.x + t) >> 5;
    int lane = t & 31;
    if (warp < N_NODES) {
        int d = warp;
        float ad = g_ad2[d];
        int beg = g_rowptr[d], end = g_rowptr[d + 1];

        float denom = 1e-16f;
        __half2 acc = __float2half2_rn(0.f);
        for (int i = beg; i < end; i++) {
            int s = g_csr_src[i];
            float w = __expf(lrelu(g_as2[s] + ad));
            denom += w;
            unsigned short u = *(const unsigned short*)&g_h2q[(size_t)s * OUT_C + lane * 2];
            acc = __hfma2(fp8x2_to_half2(u), __float2half2_rn(w), acc);
        }
        {
            float w = __expf(lrelu(g_as2[d] + ad));
            denom += w;
            unsigned short u = *(const unsigned short*)&g_h2q[(size_t)d * OUT_C + lane * 2];
            acc = __hfma2(fp8x2_to_half2(u), __float2half2_rn(w), acc);
        }
        float inv = 1.f / denom;
        float2 f = __half22float2(acc);
        float v0 = fmaxf(f.x * inv + b2[lane * 2 + 0], 0.f);
        float v1 = fmaxf(f.y * inv + b2[lane * 2 + 1], 0.f);
        atomicAdd(&sp[lane * 2 + 0], v0);
        atomicAdd(&sp[lane * 2 + 1], v1);
    }
    __syncthreads();
    if (t < OUT_C) atomicAdd(&g_pooled[t], sp[t]);
}

// ----------------------------------------------------------------------------
// Final: mean-pool scale, FC to 40 classes, log_softmax
// ----------------------------------------------------------------------------
__global__ void final_kernel(const float* __restrict__ fc_w,
                             const float* __restrict__ fc_b,
                             float* __restrict__ out) {
    __shared__ float p[OUT_C];
    __shared__ float lg[NUM_CLASSES];
    __shared__ float lse_sh;
    int t = threadIdx.x;  // 64 threads
    p[t] = g_pooled[t] * (1.0f / (float)N_NODES);
    __syncthreads();
    if (t < NUM_CLASSES) {
        float s = fc_b[t];
#pragma unroll
        for (int c = 0; c < OUT_C; c++) s += p[c] * fc_w[c * NUM_CLASSES + t];
        lg[t] = s;
    }
    __syncthreads();
    if (t == 0) {
        float mx = lg[0];
        for (int j = 1; j < NUM_CLASSES; j++) mx = fmaxf(mx, lg[j]);
        float se = 0.f;
        for (int j = 0; j < NUM_CLASSES; j++) se += expf(lg[j] - mx);
        lse_sh = mx + logf(se);
    }
    __syncthreads();
    if (t < NUM_CLASSES) out[t] = lg[t] - lse_sh;
}

// ----------------------------------------------------------------------------
// launch: CSR build (side stream) overlaps wsplit+gemm1 (main stream).
// ----------------------------------------------------------------------------
extern "C" void kernel_launch(void* const* d_in, const int* in_sizes, int n_in,
                              void* d_out, int out_size) {
    const float* x      = (const float*)d_in[0];
    const void*  ei     = d_in[1];
    const float* W1     = (const float*)d_in[2];
    const float* att_s1 = (const float*)d_in[3];
    const float* att_d1 = (const float*)d_in[4];
    const float* b1     = (const float*)d_in[5];
    const float* W2     = (const float*)d_in[6];
    const float* att_s2 = (const float*)d_in[7];
    const float* att_d2 = (const float*)d_in[8];
    const float* b2     = (const float*)d_in[9];
    const float* fc_w   = (const float*)d_in[10];
    const float* fc_b   = (const float*)d_in[11];
    float* out = (float*)d_out;

    int E = in_sizes[1] / 2;
    if (E > E_MAX) E = E_MAX;

    const int WARPS_PER_BLOCK = 8;
    const int nodeBlocks = (N_NODES + WARPS_PER_BLOCK - 1) / WARPS_PER_BLOCK;
    const int mBlocks = (N_NODES + 127) / 128;
    const int edge4Blocks = ((E + 3) / 4 + 255) / 256;

    static cudaStream_t s_side = nullptr;
    static cudaEvent_t  ev_fork = nullptr, ev_join = nullptr;
    if (s_side == nullptr) {
        cudaStreamCreateWithFlags(&s_side, cudaStreamNonBlocking);
        cudaEventCreateWithFlags(&ev_fork, cudaEventDisableTiming);
        cudaEventCreateWithFlags(&ev_join, cudaEventDisableTiming);
    }

    // Fork: CSR-build chain on side stream
    cudaEventRecord(ev_fork, 0);
    cudaStreamWaitEvent(s_side, ev_fork, 0);

    init_detect_kernel<<<(N_NODES + 256) / 256, 256, 0, s_side>>>((const int*)ei);
    count_kernel<<<edge4Blocks, 256, 0, s_side>>>(ei, E);
    scan1_kernel<<<SCAN_NBLK, SCAN_BLOCK, 0, s_side>>>();
    scan2_kernel<<<1, 64, 0, s_side>>>();
    scan3_kernel<<<SCAN_NBLK, SCAN_BLOCK, 0, s_side>>>();
    fill_kernel<<<edge4Blocks, 256, 0, s_side>>>(ei, E);
    cudaEventRecord(ev_join, s_side);

    // Concurrent on main stream: weight split + layer-1 GEMM
    wsplit_kernel<<<(IN_C * F1 + 255) / 256, 256>>>(W1, W2);
    gemm1_fused<<<dim3(F1 / 128, mBlocks), 256>>>(x, att_s1, att_d1);

    // Join: agg1 needs both CSR and gemm1
    cudaStreamWaitEvent(0, ev_join, 0);

    agg1_kernel<<<nodeBlocks, 256>>>(b1);
    gemm2_fused<<<dim3(1, mBlocks), 128>>>(att_s2, att_d2);
    agg2_pool_kernel<<<nodeBlocks, 256>>>(b2);
    final_kernel<<<1, 64>>>(fc_w, fc_b, out);
}